// round 14
// baseline (speedup 1.0000x reference)
#include <cuda_runtime.h>
#include <cuda_bf16.h>
#include <cuda_fp16.h>
#include <cstdint>
#include <cmath>

#define DIV_UP(a, b) (((a) + (b) - 1) / (b))

// Scratch (static device allocations — the only legal kind here)
__device__ __align__(16) __half g_fv_h[1 << 24];           // 33.5 MB fp16 fv
__device__ __align__(16) __half g_q_h[1 << 19];            // fp16 q (MLP out)
__device__ __align__(16) __nv_bfloat16 g_x0_hi[1 << 19];   // MLP act planes
__device__ __align__(16) __nv_bfloat16 g_x0_lo[1 << 19];
__device__ __align__(16) __nv_bfloat16 g_x1_hi[1 << 19];
__device__ __align__(16) __nv_bfloat16 g_x1_lo[1 << 19];
__device__ __align__(16) __nv_bfloat16 g_w_hi[1 << 18];    // 4 weight mats
__device__ __align__(16) __nv_bfloat16 g_w_lo[1 << 18];

// ============================================================================
// helpers
// ============================================================================
__device__ __forceinline__ uint32_t smem_to_u32(const void* smem_ptr) {
    uint32_t addr;
    asm("{ .reg .u64 tmp; cvta.to.shared.u64 tmp, %1; cvt.u32.u64 %0, tmp; }"
        : "=r"(addr) : "l"(smem_ptr));
    return addr;
}

__device__ __forceinline__ void ldmatrix_x4(uint32_t* r, uint32_t addr) {
    asm volatile("ldmatrix.sync.aligned.m8n8.x4.shared.b16 {%0,%1,%2,%3}, [%4];"
                 : "=r"(r[0]), "=r"(r[1]), "=r"(r[2]), "=r"(r[3]) : "r"(addr));
}

__device__ __forceinline__ void ldmatrix_x2(uint32_t* r, uint32_t addr) {
    asm volatile("ldmatrix.sync.aligned.m8n8.x2.shared.b16 {%0,%1}, [%2];"
                 : "=r"(r[0]), "=r"(r[1]) : "r"(addr));
}

// D += A(f16) * B(f16)^T, m16n8k16, fp32 accumulate
__device__ __forceinline__ void mma_f16(float* c, const uint32_t* a,
                                        const uint32_t* b) {
    asm volatile(
        "mma.sync.aligned.m16n8k16.row.col.f32.f16.f16.f32 "
        "{%0,%1,%2,%3}, {%4,%5,%6,%7}, {%8,%9}, {%0,%1,%2,%3};"
        : "+f"(c[0]), "+f"(c[1]), "+f"(c[2]), "+f"(c[3])
        : "r"(a[0]), "r"(a[1]), "r"(a[2]), "r"(a[3]), "r"(b[0]), "r"(b[1]));
}

// D += A(bf16) * B(bf16)^T, m16n8k16, fp32 accumulate
__device__ __forceinline__ void mma_bf16(float* c, const uint32_t* a,
                                         const uint32_t* b) {
    asm volatile(
        "mma.sync.aligned.m16n8k16.row.col.f32.bf16.bf16.f32 "
        "{%0,%1,%2,%3}, {%4,%5,%6,%7}, {%8,%9}, {%0,%1,%2,%3};"
        : "+f"(c[0]), "+f"(c[1]), "+f"(c[2]), "+f"(c[3])
        : "r"(a[0]), "r"(a[1]), "r"(a[2]), "r"(a[3]), "r"(b[0]), "r"(b[1]));
}

__device__ __forceinline__ void cp16(uint32_t smem, const void* g) {
    asm volatile("cp.async.cg.shared.global [%0], [%1], 16;"
                 :: "r"(smem), "l"(g));
}

// split fp32 pair into packed bf16x2 hi and lo planes
__device__ __forceinline__ void split2(float x, float y, uint32_t& hi, uint32_t& lo) {
    __nv_bfloat16 hx = __float2bfloat16(x);
    __nv_bfloat16 hy = __float2bfloat16(y);
    __nv_bfloat16 lx = __float2bfloat16(x - __bfloat162float(hx));
    __nv_bfloat16 ly = __float2bfloat16(y - __bfloat162float(hy));
    hi = (uint32_t)__bfloat16_as_ushort(hx) | ((uint32_t)__bfloat16_as_ushort(hy) << 16);
    lo = (uint32_t)__bfloat16_as_ushort(lx) | ((uint32_t)__bfloat16_as_ushort(ly) << 16);
}

// ============================================================================
// prep kernel: fv fp32->fp16 convert AND zero the output, one launch
// ============================================================================
__global__ void __launch_bounds__(256)
prep_kernel(const float* __restrict__ fv, __half* __restrict__ fv_h,
            float* __restrict__ outp, long n4_fv, long n4_out) {
    long i = (long)blockIdx.x * blockDim.x + threadIdx.x;
    if (i < n4_fv) {
        float4 v = reinterpret_cast<const float4*>(fv)[i];
        reinterpret_cast<__half2*>(fv_h)[2 * i + 0] = __floats2half2_rn(v.x, v.y);
        reinterpret_cast<__half2*>(fv_h)[2 * i + 1] = __floats2half2_rn(v.z, v.w);
    } else {
        long j = i - n4_fv;
        if (j < n4_out)
            reinterpret_cast<float4*>(outp)[j] = make_float4(0.f, 0.f, 0.f, 0.f);
    }
}

// ============================================================================
// conversion kernels (queries + weights)
// ============================================================================
__global__ void __launch_bounds__(256)
convert_split_kernel(const float* __restrict__ in,
                     __nv_bfloat16* __restrict__ hi,
                     __nv_bfloat16* __restrict__ lo, long n4) {
    long i = (long)blockIdx.x * blockDim.x + threadIdx.x;
    if (i >= n4) return;
    float4 v = reinterpret_cast<const float4*>(in)[i];
    uint32_t h0, l0, h1, l1;
    split2(v.x, v.y, h0, l0);
    split2(v.z, v.w, h1, l1);
    reinterpret_cast<uint2*>(hi)[i] = make_uint2(h0, h1);
    reinterpret_cast<uint2*>(lo)[i] = make_uint2(l0, l1);
}

__global__ void __launch_bounds__(256)
convert_split4_kernel(const float* __restrict__ w0, const float* __restrict__ w1,
                      const float* __restrict__ w2, const float* __restrict__ w3,
                      __nv_bfloat16* __restrict__ hi,
                      __nv_bfloat16* __restrict__ lo, long w4) {
    long i = (long)blockIdx.x * blockDim.x + threadIdx.x;
    if (i >= 4 * w4) return;
    int m = (int)(i / w4);
    long j = i - (long)m * w4;
    const float* src = (m == 0) ? w0 : (m == 1) ? w1 : (m == 2) ? w2 : w3;
    float4 v = reinterpret_cast<const float4*>(src)[j];
    uint32_t h0, l0, h1, l1;
    split2(v.x, v.y, h0, l0);
    split2(v.z, v.w, h1, l1);
    reinterpret_cast<uint2*>(hi)[i] = make_uint2(h0, h1);
    reinterpret_cast<uint2*>(lo)[i] = make_uint2(l0, l1);
}

// ============================================================================
// MLP layer via tensor cores (R12 proven shape): Y = act(X @ W^T + bias).
// CTA 64(m)x64(n), 4 warps 2x2, warp tile 32x32, KC=64 double-buffered.
// LAST=1: writes fp16 q_h (no relu); else writes bf16 hi/lo act planes.
// ============================================================================
constexpr int MKC   = 64;
constexpr int MLDS  = MKC + 8;                       // bf16 stride
constexpr int M_A_HI = 0;
constexpr int M_A_LO = M_A_HI + 64 * MLDS * 2;       // 9216
constexpr int M_B_HI = M_A_LO + 64 * MLDS * 2;       // 18432
constexpr int M_B_LO = M_B_HI + 64 * MLDS * 2;       // 27648
constexpr int M_BUF  = M_B_LO + 64 * MLDS * 2;       // 36864
constexpr int MLP_SMEM = 2 * M_BUF;                  // 73728

template <int RELU, int LAST>
__global__ void __launch_bounds__(128)
mlp_mma_kernel(const __nv_bfloat16* __restrict__ x_hi,
               const __nv_bfloat16* __restrict__ x_lo,
               const __nv_bfloat16* __restrict__ w_hi,
               const __nv_bfloat16* __restrict__ w_lo,
               const float* __restrict__ bias,
               __nv_bfloat16* __restrict__ y_hi,
               __nv_bfloat16* __restrict__ y_lo,
               __half* __restrict__ yh,
               int M, int K, int N) {
    extern __shared__ __align__(16) char smem[];
    const uint32_t sbase = smem_to_u32(smem);

    const int tid  = threadIdx.x;
    const int wid  = tid >> 5;
    const int lane = tid & 31;
    const int n0 = blockIdx.x * 64;
    const int m0 = blockIdx.y * 64;

    const int warp_m = (wid & 1) * 32;
    const int warp_n = (wid >> 1) * 32;

    float c[2][4][4] = {};

    const int nch = K / MKC;

    auto load_chunk = [&](int cc) {
        const int k0 = cc * MKC;
        const uint32_t bb = sbase + (uint32_t)(cc & 1) * M_BUF;
        #pragma unroll
        for (int i = 0; i < 4; ++i) {
            int idx = tid + i * 128;
            int row = idx >> 3;
            int seg = (idx & 7) * 8;
            int m = m0 + row; if (m >= M) m = M - 1;
            long gg = (long)m * K + k0 + seg;
            uint32_t soff = (uint32_t)((row * MLDS + seg) * 2);
            cp16(bb + M_A_HI + soff, x_hi + gg);
            cp16(bb + M_A_LO + soff, x_lo + gg);
        }
        #pragma unroll
        for (int i = 0; i < 4; ++i) {
            int idx = tid + i * 128;
            int row = idx >> 3;
            int seg = (idx & 7) * 8;
            long gg = (long)(n0 + row) * K + k0 + seg;
            uint32_t soff = (uint32_t)((row * MLDS + seg) * 2);
            cp16(bb + M_B_HI + soff, w_hi + gg);
            cp16(bb + M_B_LO + soff, w_lo + gg);
        }
        asm volatile("cp.async.commit_group;" ::: "memory");
    };

    load_chunk(0);

    for (int cc = 0; cc < nch; ++cc) {
        if (cc + 1 < nch) {
            load_chunk(cc + 1);
            asm volatile("cp.async.wait_group 1;" ::: "memory");
        } else {
            asm volatile("cp.async.wait_group 0;" ::: "memory");
        }
        __syncthreads();

        const uint32_t bb = sbase + (uint32_t)(cc & 1) * M_BUF;
        const uint32_t ah_s = bb + M_A_HI;
        const uint32_t al_s = bb + M_A_LO;
        const uint32_t bh_s = bb + M_B_HI;
        const uint32_t bl_s = bb + M_B_LO;

        #pragma unroll
        for (int kk = 0; kk < MKC; kk += 16) {
            uint32_t ah[2][4], al[2][4];
            #pragma unroll
            for (int mi = 0; mi < 2; ++mi) {
                int row = warp_m + mi * 16 + (lane & 15);
                int col = kk + ((lane >> 4) << 3);
                uint32_t addr = (uint32_t)((row * MLDS + col) * 2);
                ldmatrix_x4(ah[mi], ah_s + addr);
                ldmatrix_x4(al[mi], al_s + addr);
            }
            uint32_t bh[4][2], bl[4][2];
            #pragma unroll
            for (int nb = 0; nb < 2; ++nb) {
                int row = warp_n + nb * 16 + ((lane & 16) >> 1) + (lane & 7);
                int col = kk + ((lane >> 3) & 1) * 8;
                uint32_t addr = (uint32_t)((row * MLDS + col) * 2);
                uint32_t rh[4], rl[4];
                ldmatrix_x4(rh, bh_s + addr);
                ldmatrix_x4(rl, bl_s + addr);
                bh[nb * 2 + 0][0] = rh[0]; bh[nb * 2 + 0][1] = rh[1];
                bh[nb * 2 + 1][0] = rh[2]; bh[nb * 2 + 1][1] = rh[3];
                bl[nb * 2 + 0][0] = rl[0]; bl[nb * 2 + 0][1] = rl[1];
                bl[nb * 2 + 1][0] = rl[2]; bl[nb * 2 + 1][1] = rl[3];
            }
            #pragma unroll
            for (int mi = 0; mi < 2; ++mi) {
                #pragma unroll
                for (int ni = 0; ni < 4; ++ni) {
                    mma_bf16(c[mi][ni], ah[mi], bh[ni]);
                    mma_bf16(c[mi][ni], ah[mi], bl[ni]);
                    mma_bf16(c[mi][ni], al[mi], bh[ni]);
                }
            }
        }
        __syncthreads();
    }

    #pragma unroll
    for (int mi = 0; mi < 2; ++mi) {
        #pragma unroll
        for (int half = 0; half < 2; ++half) {
            int m = m0 + warp_m + mi * 16 + half * 8 + (lane >> 2);
            if (m >= M) continue;
            #pragma unroll
            for (int ni = 0; ni < 4; ++ni) {
                int n = n0 + warp_n + ni * 8 + 2 * (lane & 3);
                float v0 = c[mi][ni][half * 2 + 0] + bias[n];
                float v1 = c[mi][ni][half * 2 + 1] + bias[n + 1];
                if (LAST) {
                    *reinterpret_cast<__half2*>(yh + (long)m * N + n) =
                        __floats2half2_rn(v0, v1);
                } else {
                    if (RELU) { v0 = fmaxf(v0, 0.f); v1 = fmaxf(v1, 0.f); }
                    uint32_t h, l;
                    split2(v0, v1, h, l);
                    long o = ((long)m * N + n) >> 1;
                    reinterpret_cast<uint32_t*>(y_hi)[o] = h;
                    reinterpret_cast<uint32_t*>(y_lo)[o] = l;
                }
            }
        }
    }
}

// ============================================================================
// Logits GEMM v4: B-persistent q tile (160 x 256 fp16), f-looping with
// 64-row subtiles, double-buffered A. 256 threads, 8 warps 2m x 4n,
// warp tile 32x40. 2 CTAs/SM -> cross-CTA overlap of sync/epilogue bubbles.
// ============================================================================
constexpr int LQT  = 160;
constexpr int LFS  = 64;         // f-subtile rows
constexpr int LKC  = 32;
constexpr int LDA2 = LKC + 8;    // A fp16 stride (40)
constexpr int LDB2 = 256 + 8;    // B fp16 stride (264), D=256
constexpr int L_B_OFF  = 0;
constexpr int L_B_SZ   = LQT * LDB2 * 2;             // 84480
constexpr int L_A_OFF  = L_B_SZ;
constexpr int L_A_BUF  = LFS * LDA2 * 2;             // 5120
constexpr int LOGITS_SMEM = L_A_OFF + 2 * L_A_BUF;   // 94720 (x2 = 185 KB)

__global__ void __launch_bounds__(256, 2)
logits_mma_kernel(const __half* __restrict__ fv_h,   // [B*F, D] fp16
                  const __half* __restrict__ q_h,    // [B*Q, D] fp16
                  const int* __restrict__ fidx,      // [B*F, 3]
                  float* __restrict__ out,
                  const int* __restrict__ width_ptr, int width_imm,
                  int F, int Q, int D, long HWQ) {
    extern __shared__ __align__(16) char smem[];
    const uint32_t sbase = smem_to_u32(smem);

    const int tid  = threadIdx.x;
    const int wid  = tid >> 5;
    const int lane = tid & 31;
    const int qt = blockIdx.x;
    const int g  = blockIdx.y;
    const int G  = gridDim.y;
    const int b  = blockIdx.z;
    const int q0 = qt * LQT;

    const int warp_m = (wid & 1) * 32;       // 2 m-warps x 32 rows
    const int warp_n = (wid >> 1) * 40;      // 4 n-warps x 40 cols

    const long fbase = (long)b * F;
    const long brow0 = (long)b * Q;
    const int Wd = width_ptr ? *width_ptr : width_imm;

    // ---- load persistent B tile: 160 q-rows x full K (clamped) ----
    {
        const int kq = D >> 3;                       // 16B ops per row (32)
        for (int i = tid; i < LQT * kq; i += 256) {
            int row = i / kq;
            int seg = (i - row * kq) * 8;
            int q = q0 + row;
            if (q >= Q) q = Q - 1;                   // masked in epilogue
            cp16(sbase + L_B_OFF + (uint32_t)((row * LDB2 + seg) * 2),
                 q_h + (brow0 + q) * (long)D + seg);
        }
        asm volatile("cp.async.commit_group;" ::: "memory");
    }

    const int nsub = F / LFS;
    const int nmy = (g < nsub) ? (nsub - 1 - g) / G + 1 : 0;
    const int T = nmy * 8;                           // D/LKC == 8 chunks

    auto load_A = [&](int t) {
        int i_sub = t >> 3, kc = t & 7, buf = t & 1;
        long f0 = (long)(g + i_sub * G) * LFS;
        int row = tid >> 2;                          // 0..63
        int seg = (tid & 3) * 8;
        long gg = (fbase + f0 + row) * D + kc * LKC + seg;
        cp16(sbase + L_A_OFF + (uint32_t)buf * L_A_BUF +
                 (uint32_t)((row * LDA2 + seg) * 2),
             fv_h + gg);
        asm volatile("cp.async.commit_group;" ::: "memory");
    };

    if (T > 0) load_A(0);

    int t = 0;
    for (int i = 0; i < nmy; ++i) {
        const int f0 = (g + i * G) * LFS;

        // prefetch scatter indices for this subtile
        int hh[4], ww[4];
        #pragma unroll
        for (int mi = 0; mi < 2; ++mi) {
            #pragma unroll
            for (int half = 0; half < 2; ++half) {
                int row = warp_m + mi * 16 + half * 8 + (lane >> 2);
                long n = fbase + f0 + row;
                hh[mi * 2 + half] = fidx[3 * n + 1];
                ww[mi * 2 + half] = fidx[3 * n + 2];
            }
        }

        float c[2][5][4] = {};

        for (int kc = 0; kc < 8; ++kc, ++t) {
            if (t + 1 < T) {
                load_A(t + 1);
                asm volatile("cp.async.wait_group 1;" ::: "memory");
            } else {
                asm volatile("cp.async.wait_group 0;" ::: "memory");
            }
            __syncthreads();

            const uint32_t as = sbase + L_A_OFF + (uint32_t)(t & 1) * L_A_BUF;

            #pragma unroll
            for (int kk = 0; kk < LKC; kk += 16) {
                uint32_t a[2][4];
                #pragma unroll
                for (int mi = 0; mi < 2; ++mi) {
                    int row = warp_m + mi * 16 + (lane & 15);
                    int col = kk + ((lane >> 4) << 3);
                    ldmatrix_x4(a[mi], as + (uint32_t)((row * LDA2 + col) * 2));
                }
                uint32_t bf[5][2];
                {
                    int col = kc * LKC + kk + ((lane >> 3) & 1) * 8;
                    int r1 = warp_n + ((lane & 16) >> 1) + (lane & 7);
                    uint32_t r[4];
                    ldmatrix_x4(r, sbase + L_B_OFF +
                                       (uint32_t)((r1 * LDB2 + col) * 2));
                    bf[0][0] = r[0]; bf[0][1] = r[1];
                    bf[1][0] = r[2]; bf[1][1] = r[3];
                    ldmatrix_x4(r, sbase + L_B_OFF +
                                       (uint32_t)(((r1 + 16) * LDB2 + col) * 2));
                    bf[2][0] = r[0]; bf[2][1] = r[1];
                    bf[3][0] = r[2]; bf[3][1] = r[3];
                    int r2 = warp_n + 32 + (lane & 7);
                    ldmatrix_x2(bf[4], sbase + L_B_OFF +
                                           (uint32_t)((r2 * LDB2 + col) * 2));
                }
                #pragma unroll
                for (int mi = 0; mi < 2; ++mi) {
                    #pragma unroll
                    for (int ni = 0; ni < 5; ++ni) {
                        mma_f16(c[mi][ni], a[mi], bf[ni]);
                    }
                }
            }
            __syncthreads();
        }

        // ---- epilogue for this subtile: lane-paired float4 atomics ----
        #pragma unroll
        for (int mi = 0; mi < 2; ++mi) {
            #pragma unroll
            for (int half = 0; half < 2; ++half) {
                int row = warp_m + mi * 16 + half * 8 + (lane >> 2);
                int f = f0 + row;
                bool ok = (f < F);
                long obase = (long)b * HWQ +
                             ((long)hh[mi * 2 + half] * Wd + ww[mi * 2 + half]) *
                                 (long)Q;
                #pragma unroll
                for (int ni = 0; ni < 5; ++ni) {
                    float v0 = c[mi][ni][half * 2 + 0];
                    float v1 = c[mi][ni][half * 2 + 1];
                    float p0 = __shfl_xor_sync(0xFFFFFFFFu, v0, 1);
                    float p1 = __shfl_xor_sync(0xFFFFFFFFu, v1, 1);
                    if (ok && (lane & 1) == 0) {
                        int q = q0 + warp_n + ni * 8 + 2 * (lane & 3);
                        if (q + 3 < Q) {
                            atomicAdd(reinterpret_cast<float4*>(out + obase + q),
                                      make_float4(v0, v1, p0, p1));
                        } else {
                            if (q     < Q) atomicAdd(out + obase + q,     v0);
                            if (q + 1 < Q) atomicAdd(out + obase + q + 1, v1);
                            if (q + 2 < Q) atomicAdd(out + obase + q + 2, p0);
                            if (q + 3 < Q) atomicAdd(out + obase + q + 3, p1);
                        }
                    }
                }
            }
        }
    }
}

// ---------------------------------------------------------------------------
static int isqrt_host(long v) {
    int r = (int)(sqrt((double)v) + 0.5);
    while ((long)r * r > v) --r;
    while ((long)(r + 1) * (r + 1) <= v) ++r;
    return r;
}

extern "C" void kernel_launch(void* const* d_in, const int* in_sizes, int n_in,
                              void* d_out, int out_size) {
    const float* queries = (const float*)d_in[0];
    const float* fv      = (const float*)d_in[1];
    const int*   fidx    = (const int*)d_in[2];

    bool scalars_present = (n_in >= 15 && in_sizes[5] == 1 && in_sizes[6] == 1);
    int wbase = scalars_present ? 7 : 5;
    const int* width_ptr = scalars_present ? (const int*)d_in[6] : nullptr;

    const float* Wl[4];
    const float* bl[4];
    for (int i = 0; i < 4; ++i) {
        Wl[i] = (const float*)d_in[wbase + 2 * i];
        bl[i] = (const float*)d_in[wbase + 2 * i + 1];
    }

    const int D  = in_sizes[wbase + 1];       // len(b0)
    const int Mq = in_sizes[0] / D;           // B*Q
    const int B  = in_sizes[3] - 1;
    const int Q  = Mq / B;
    const int NF = in_sizes[1] / D;           // B*F
    const int F  = NF / B;
    const long HWQ = (long)out_size / B;      // H*W*Q
    const int width_imm = isqrt_host(HWQ / Q);

    __half *fv_h = nullptr, *q_h = nullptr;
    __nv_bfloat16 *x0h = nullptr, *x0l = nullptr, *x1h = nullptr, *x1l = nullptr;
    __nv_bfloat16 *wh = nullptr, *wl = nullptr;
    cudaGetSymbolAddress((void**)&fv_h, g_fv_h);
    cudaGetSymbolAddress((void**)&q_h, g_q_h);
    cudaGetSymbolAddress((void**)&x0h, g_x0_hi);
    cudaGetSymbolAddress((void**)&x0l, g_x0_lo);
    cudaGetSymbolAddress((void**)&x1h, g_x1_hi);
    cudaGetSymbolAddress((void**)&x1l, g_x1_lo);
    cudaGetSymbolAddress((void**)&wh, g_w_hi);
    cudaGetSymbolAddress((void**)&wl, g_w_lo);

    static cudaStream_t side1 = nullptr;
    static cudaEvent_t ev_fork = nullptr, ev_w = nullptr, ev_j1 = nullptr;
    static bool attr_done = false;
    if (!side1) {
        cudaStreamCreateWithFlags(&side1, cudaStreamNonBlocking);
        cudaEventCreateWithFlags(&ev_fork, cudaEventDisableTiming);
        cudaEventCreateWithFlags(&ev_w, cudaEventDisableTiming);
        cudaEventCreateWithFlags(&ev_j1, cudaEventDisableTiming);
    }
    if (!attr_done) {
        cudaFuncSetAttribute(logits_mma_kernel,
                             cudaFuncAttributeMaxDynamicSharedMemorySize,
                             LOGITS_SMEM);
        cudaFuncSetAttribute(mlp_mma_kernel<1, 0>,
                             cudaFuncAttributeMaxDynamicSharedMemorySize,
                             MLP_SMEM);
        cudaFuncSetAttribute(mlp_mma_kernel<0, 1>,
                             cudaFuncAttributeMaxDynamicSharedMemorySize,
                             MLP_SMEM);
        attr_done = true;
    }

    // ---- fork: side1 runs weight split, then prep (fv convert + zero out) ----
    cudaEventRecord(ev_fork, 0);
    cudaStreamWaitEvent(side1, ev_fork, 0);
    {
        long w4 = (long)D * D / 4;
        convert_split4_kernel<<<(int)DIV_UP(4 * w4, 256L), 256, 0, side1>>>(
            Wl[0], Wl[1], Wl[2], Wl[3], wh, wl, w4);
        cudaEventRecord(ev_w, side1);
        long n4_fv = (long)NF * D / 4;
        long n4_out = (long)out_size / 4;
        long total = n4_fv + n4_out;
        prep_kernel<<<(int)DIV_UP(total, 256L), 256, 0, side1>>>(
            fv, fv_h, (float*)d_out, n4_fv, n4_out);
    }

    // main: query split, then 4 tensor-core MLP layers (after weights ready)
    {
        long n4 = (long)Mq * D / 4;
        convert_split_kernel<<<(int)DIV_UP(n4, 256L), 256>>>(queries, x0h, x0l, n4);
    }
    cudaStreamWaitEvent(0, ev_w, 0);
    {
        dim3 grid(D / 64, DIV_UP(Mq, 64));
        long wsz = (long)D * D;
        mlp_mma_kernel<1, 0><<<grid, 128, MLP_SMEM>>>(
            x0h, x0l, wh + 0 * wsz, wl + 0 * wsz, bl[0], x1h, x1l, nullptr,
            Mq, D, D);
        mlp_mma_kernel<1, 0><<<grid, 128, MLP_SMEM>>>(
            x1h, x1l, wh + 1 * wsz, wl + 1 * wsz, bl[1], x0h, x0l, nullptr,
            Mq, D, D);
        mlp_mma_kernel<1, 0><<<grid, 128, MLP_SMEM>>>(
            x0h, x0l, wh + 2 * wsz, wl + 2 * wsz, bl[2], x1h, x1l, nullptr,
            Mq, D, D);
        mlp_mma_kernel<0, 1><<<grid, 128, MLP_SMEM>>>(
            x1h, x1l, wh + 3 * wsz, wl + 3 * wsz, bl[3], nullptr, nullptr, q_h,
            Mq, D, D);
    }

    // ---- join ----
    cudaEventRecord(ev_j1, side1);
    cudaStreamWaitEvent(0, ev_j1, 0);

    // Logits GEMM v4 (B-persistent, 2 CTAs/SM) fused with scatter-add
    {
        int nsub = F / LFS;              // 256 for F=16384
        int G = nsub / 8;                // 32 -> 8 subtiles per CTA
        if (G < 1) G = 1;
        dim3 grid(DIV_UP(Q, LQT), G, B);
        logits_mma_kernel<<<grid, 256, LOGITS_SMEM>>>(fv_h, q_h, fidx,
                                                      (float*)d_out,
                                                      width_ptr, width_imm,
                                                      F, Q, D, HWQ);
    }
}

// round 15
// speedup vs baseline: 1.2561x; 1.2561x over previous
#include <cuda_runtime.h>
#include <cuda_bf16.h>
#include <cuda_fp16.h>
#include <cstdint>
#include <cmath>

#define DIV_UP(a, b) (((a) + (b) - 1) / (b))

// Scratch (static device allocations — the only legal kind here)
__device__ __align__(16) __half g_fv_h[1 << 24];           // 33.5 MB fp16 fv
__device__ __align__(16) __half g_q_h[1 << 19];            // fp16 q (MLP out)
__device__ __align__(16) __nv_bfloat16 g_x0_hi[1 << 19];   // MLP act planes
__device__ __align__(16) __nv_bfloat16 g_x0_lo[1 << 19];
__device__ __align__(16) __nv_bfloat16 g_x1_hi[1 << 19];
__device__ __align__(16) __nv_bfloat16 g_x1_lo[1 << 19];
__device__ __align__(16) __nv_bfloat16 g_w_hi[1 << 18];    // 4 weight mats
__device__ __align__(16) __nv_bfloat16 g_w_lo[1 << 18];

// ============================================================================
// helpers
// ============================================================================
__device__ __forceinline__ uint32_t smem_to_u32(const void* smem_ptr) {
    uint32_t addr;
    asm("{ .reg .u64 tmp; cvta.to.shared.u64 tmp, %1; cvt.u32.u64 %0, tmp; }"
        : "=r"(addr) : "l"(smem_ptr));
    return addr;
}

__device__ __forceinline__ void ldmatrix_x4(uint32_t* r, uint32_t addr) {
    asm volatile("ldmatrix.sync.aligned.m8n8.x4.shared.b16 {%0,%1,%2,%3}, [%4];"
                 : "=r"(r[0]), "=r"(r[1]), "=r"(r[2]), "=r"(r[3]) : "r"(addr));
}

__device__ __forceinline__ void ldmatrix_x2(uint32_t* r, uint32_t addr) {
    asm volatile("ldmatrix.sync.aligned.m8n8.x2.shared.b16 {%0,%1}, [%2];"
                 : "=r"(r[0]), "=r"(r[1]) : "r"(addr));
}

// D += A(f16) * B(f16)^T, m16n8k16, fp32 accumulate
__device__ __forceinline__ void mma_f16(float* c, const uint32_t* a,
                                        const uint32_t* b) {
    asm volatile(
        "mma.sync.aligned.m16n8k16.row.col.f32.f16.f16.f32 "
        "{%0,%1,%2,%3}, {%4,%5,%6,%7}, {%8,%9}, {%0,%1,%2,%3};"
        : "+f"(c[0]), "+f"(c[1]), "+f"(c[2]), "+f"(c[3])
        : "r"(a[0]), "r"(a[1]), "r"(a[2]), "r"(a[3]), "r"(b[0]), "r"(b[1]));
}

// D += A(bf16) * B(bf16)^T, m16n8k16, fp32 accumulate
__device__ __forceinline__ void mma_bf16(float* c, const uint32_t* a,
                                         const uint32_t* b) {
    asm volatile(
        "mma.sync.aligned.m16n8k16.row.col.f32.bf16.bf16.f32 "
        "{%0,%1,%2,%3}, {%4,%5,%6,%7}, {%8,%9}, {%0,%1,%2,%3};"
        : "+f"(c[0]), "+f"(c[1]), "+f"(c[2]), "+f"(c[3])
        : "r"(a[0]), "r"(a[1]), "r"(a[2]), "r"(a[3]), "r"(b[0]), "r"(b[1]));
}

__device__ __forceinline__ void cp16(uint32_t smem, const void* g) {
    asm volatile("cp.async.cg.shared.global [%0], [%1], 16;"
                 :: "r"(smem), "l"(g));
}

// split fp32 pair into packed bf16x2 hi and lo planes
__device__ __forceinline__ void split2(float x, float y, uint32_t& hi, uint32_t& lo) {
    __nv_bfloat16 hx = __float2bfloat16(x);
    __nv_bfloat16 hy = __float2bfloat16(y);
    __nv_bfloat16 lx = __float2bfloat16(x - __bfloat162float(hx));
    __nv_bfloat16 ly = __float2bfloat16(y - __bfloat162float(hy));
    hi = (uint32_t)__bfloat16_as_ushort(hx) | ((uint32_t)__bfloat16_as_ushort(hy) << 16);
    lo = (uint32_t)__bfloat16_as_ushort(lx) | ((uint32_t)__bfloat16_as_ushort(ly) << 16);
}

// ============================================================================
// prep kernel: fv fp32->fp16 convert AND zero the output, one launch
// ============================================================================
__global__ void __launch_bounds__(256)
prep_kernel(const float* __restrict__ fv, __half* __restrict__ fv_h,
            float* __restrict__ outp, long n4_fv, long n4_out) {
    long i = (long)blockIdx.x * blockDim.x + threadIdx.x;
    if (i < n4_fv) {
        float4 v = reinterpret_cast<const float4*>(fv)[i];
        reinterpret_cast<__half2*>(fv_h)[2 * i + 0] = __floats2half2_rn(v.x, v.y);
        reinterpret_cast<__half2*>(fv_h)[2 * i + 1] = __floats2half2_rn(v.z, v.w);
    } else {
        long j = i - n4_fv;
        if (j < n4_out)
            reinterpret_cast<float4*>(outp)[j] = make_float4(0.f, 0.f, 0.f, 0.f);
    }
}

// ============================================================================
// conversion kernels (queries + weights)
// ============================================================================
__global__ void __launch_bounds__(256)
convert_split_kernel(const float* __restrict__ in,
                     __nv_bfloat16* __restrict__ hi,
                     __nv_bfloat16* __restrict__ lo, long n4) {
    long i = (long)blockIdx.x * blockDim.x + threadIdx.x;
    if (i >= n4) return;
    float4 v = reinterpret_cast<const float4*>(in)[i];
    uint32_t h0, l0, h1, l1;
    split2(v.x, v.y, h0, l0);
    split2(v.z, v.w, h1, l1);
    reinterpret_cast<uint2*>(hi)[i] = make_uint2(h0, h1);
    reinterpret_cast<uint2*>(lo)[i] = make_uint2(l0, l1);
}

__global__ void __launch_bounds__(256)
convert_split4_kernel(const float* __restrict__ w0, const float* __restrict__ w1,
                      const float* __restrict__ w2, const float* __restrict__ w3,
                      __nv_bfloat16* __restrict__ hi,
                      __nv_bfloat16* __restrict__ lo, long w4) {
    long i = (long)blockIdx.x * blockDim.x + threadIdx.x;
    if (i >= 4 * w4) return;
    int m = (int)(i / w4);
    long j = i - (long)m * w4;
    const float* src = (m == 0) ? w0 : (m == 1) ? w1 : (m == 2) ? w2 : w3;
    float4 v = reinterpret_cast<const float4*>(src)[j];
    uint32_t h0, l0, h1, l1;
    split2(v.x, v.y, h0, l0);
    split2(v.z, v.w, h1, l1);
    reinterpret_cast<uint2*>(hi)[i] = make_uint2(h0, h1);
    reinterpret_cast<uint2*>(lo)[i] = make_uint2(l0, l1);
}

// ============================================================================
// MLP layer via tensor cores (R12 proven shape): Y = act(X @ W^T + bias).
// CTA 64(m)x64(n), 4 warps 2x2, warp tile 32x32, KC=64 double-buffered.
// LAST=1: writes fp16 q_h (no relu); else writes bf16 hi/lo act planes.
// ============================================================================
constexpr int MKC   = 64;
constexpr int MLDS  = MKC + 8;                       // bf16 stride
constexpr int M_A_HI = 0;
constexpr int M_A_LO = M_A_HI + 64 * MLDS * 2;       // 9216
constexpr int M_B_HI = M_A_LO + 64 * MLDS * 2;       // 18432
constexpr int M_B_LO = M_B_HI + 64 * MLDS * 2;       // 27648
constexpr int M_BUF  = M_B_LO + 64 * MLDS * 2;       // 36864
constexpr int MLP_SMEM = 2 * M_BUF;                  // 73728

template <int RELU, int LAST>
__global__ void __launch_bounds__(128)
mlp_mma_kernel(const __nv_bfloat16* __restrict__ x_hi,
               const __nv_bfloat16* __restrict__ x_lo,
               const __nv_bfloat16* __restrict__ w_hi,
               const __nv_bfloat16* __restrict__ w_lo,
               const float* __restrict__ bias,
               __nv_bfloat16* __restrict__ y_hi,
               __nv_bfloat16* __restrict__ y_lo,
               __half* __restrict__ yh,
               int M, int K, int N) {
    extern __shared__ __align__(16) char smem[];
    const uint32_t sbase = smem_to_u32(smem);

    const int tid  = threadIdx.x;
    const int wid  = tid >> 5;
    const int lane = tid & 31;
    const int n0 = blockIdx.x * 64;
    const int m0 = blockIdx.y * 64;

    const int warp_m = (wid & 1) * 32;
    const int warp_n = (wid >> 1) * 32;

    float c[2][4][4] = {};

    const int nch = K / MKC;

    auto load_chunk = [&](int cc) {
        const int k0 = cc * MKC;
        const uint32_t bb = sbase + (uint32_t)(cc & 1) * M_BUF;
        #pragma unroll
        for (int i = 0; i < 4; ++i) {
            int idx = tid + i * 128;
            int row = idx >> 3;
            int seg = (idx & 7) * 8;
            int m = m0 + row; if (m >= M) m = M - 1;
            long gg = (long)m * K + k0 + seg;
            uint32_t soff = (uint32_t)((row * MLDS + seg) * 2);
            cp16(bb + M_A_HI + soff, x_hi + gg);
            cp16(bb + M_A_LO + soff, x_lo + gg);
        }
        #pragma unroll
        for (int i = 0; i < 4; ++i) {
            int idx = tid + i * 128;
            int row = idx >> 3;
            int seg = (idx & 7) * 8;
            long gg = (long)(n0 + row) * K + k0 + seg;
            uint32_t soff = (uint32_t)((row * MLDS + seg) * 2);
            cp16(bb + M_B_HI + soff, w_hi + gg);
            cp16(bb + M_B_LO + soff, w_lo + gg);
        }
        asm volatile("cp.async.commit_group;" ::: "memory");
    };

    load_chunk(0);

    for (int cc = 0; cc < nch; ++cc) {
        if (cc + 1 < nch) {
            load_chunk(cc + 1);
            asm volatile("cp.async.wait_group 1;" ::: "memory");
        } else {
            asm volatile("cp.async.wait_group 0;" ::: "memory");
        }
        __syncthreads();

        const uint32_t bb = sbase + (uint32_t)(cc & 1) * M_BUF;
        const uint32_t ah_s = bb + M_A_HI;
        const uint32_t al_s = bb + M_A_LO;
        const uint32_t bh_s = bb + M_B_HI;
        const uint32_t bl_s = bb + M_B_LO;

        #pragma unroll
        for (int kk = 0; kk < MKC; kk += 16) {
            uint32_t ah[2][4], al[2][4];
            #pragma unroll
            for (int mi = 0; mi < 2; ++mi) {
                int row = warp_m + mi * 16 + (lane & 15);
                int col = kk + ((lane >> 4) << 3);
                uint32_t addr = (uint32_t)((row * MLDS + col) * 2);
                ldmatrix_x4(ah[mi], ah_s + addr);
                ldmatrix_x4(al[mi], al_s + addr);
            }
            uint32_t bh[4][2], bl[4][2];
            #pragma unroll
            for (int nb = 0; nb < 2; ++nb) {
                int row = warp_n + nb * 16 + ((lane & 16) >> 1) + (lane & 7);
                int col = kk + ((lane >> 3) & 1) * 8;
                uint32_t addr = (uint32_t)((row * MLDS + col) * 2);
                uint32_t rh[4], rl[4];
                ldmatrix_x4(rh, bh_s + addr);
                ldmatrix_x4(rl, bl_s + addr);
                bh[nb * 2 + 0][0] = rh[0]; bh[nb * 2 + 0][1] = rh[1];
                bh[nb * 2 + 1][0] = rh[2]; bh[nb * 2 + 1][1] = rh[3];
                bl[nb * 2 + 0][0] = rl[0]; bl[nb * 2 + 0][1] = rl[1];
                bl[nb * 2 + 1][0] = rl[2]; bl[nb * 2 + 1][1] = rl[3];
            }
            #pragma unroll
            for (int mi = 0; mi < 2; ++mi) {
                #pragma unroll
                for (int ni = 0; ni < 4; ++ni) {
                    mma_bf16(c[mi][ni], ah[mi], bh[ni]);
                    mma_bf16(c[mi][ni], ah[mi], bl[ni]);
                    mma_bf16(c[mi][ni], al[mi], bh[ni]);
                }
            }
        }
        __syncthreads();
    }

    #pragma unroll
    for (int mi = 0; mi < 2; ++mi) {
        #pragma unroll
        for (int half = 0; half < 2; ++half) {
            int m = m0 + warp_m + mi * 16 + half * 8 + (lane >> 2);
            if (m >= M) continue;
            #pragma unroll
            for (int ni = 0; ni < 4; ++ni) {
                int n = n0 + warp_n + ni * 8 + 2 * (lane & 3);
                float v0 = c[mi][ni][half * 2 + 0] + bias[n];
                float v1 = c[mi][ni][half * 2 + 1] + bias[n + 1];
                if (LAST) {
                    *reinterpret_cast<__half2*>(yh + (long)m * N + n) =
                        __floats2half2_rn(v0, v1);
                } else {
                    if (RELU) { v0 = fmaxf(v0, 0.f); v1 = fmaxf(v1, 0.f); }
                    uint32_t h, l;
                    split2(v0, v1, h, l);
                    long o = ((long)m * N + n) >> 1;
                    reinterpret_cast<uint32_t*>(y_hi)[o] = h;
                    reinterpret_cast<uint32_t*>(y_lo)[o] = l;
                }
            }
        }
    }
}

// ============================================================================
// Logits GEMM v3.1 (R13 proven): B-persistent q tile, f-looping,
// TRIPLE-buffered A, uniform single-wave grid (G=16 -> 128 CTAs x 8 subtiles).
// 512 threads, 16 warps 4m x 4n, warp tile 32x40.
// ============================================================================
constexpr int LQT  = 160;
constexpr int LF   = 128;
constexpr int LKC  = 32;
constexpr int LDA2 = LKC + 8;    // A fp16 stride (40)
constexpr int LDB2 = 256 + 8;    // B fp16 stride (264), D=256
constexpr int L_B_OFF  = 0;
constexpr int L_B_SZ   = LQT * LDB2 * 2;             // 84480
constexpr int L_A_OFF  = L_B_SZ;
constexpr int L_A_BUF  = LF * LDA2 * 2;              // 10240
constexpr int LOGITS_SMEM = L_A_OFF + 3 * L_A_BUF;   // 115200

__global__ void __launch_bounds__(512, 1)
logits_mma_kernel(const __half* __restrict__ fv_h,   // [B*F, D] fp16
                  const __half* __restrict__ q_h,    // [B*Q, D] fp16
                  const int* __restrict__ fidx,      // [B*F, 3]
                  float* __restrict__ out,
                  const int* __restrict__ width_ptr, int width_imm,
                  int F, int Q, int D, long HWQ) {
    extern __shared__ __align__(16) char smem[];
    const uint32_t sbase = smem_to_u32(smem);

    const int tid  = threadIdx.x;
    const int wid  = tid >> 5;
    const int lane = tid & 31;
    const int qt = blockIdx.x;
    const int g  = blockIdx.y;
    const int G  = gridDim.y;
    const int b  = blockIdx.z;
    const int q0 = qt * LQT;

    const int warp_m = (wid & 3) * 32;       // 4 m-warps x 32 rows
    const int warp_n = (wid >> 2) * 40;      // 4 n-warps x 40 cols

    const long fbase = (long)b * F;
    const long brow0 = (long)b * Q;
    const int Wd = width_ptr ? *width_ptr : width_imm;

    // ---- load persistent B tile: 160 q-rows x full K (clamped) ----
    {
        const int kq = D >> 3;                       // 16B ops per row (32)
        for (int i = tid; i < LQT * kq; i += 512) {
            int row = i / kq;
            int seg = (i - row * kq) * 8;
            int q = q0 + row;
            if (q >= Q) q = Q - 1;                   // masked in epilogue
            cp16(sbase + L_B_OFF + (uint32_t)((row * LDB2 + seg) * 2),
                 q_h + (brow0 + q) * (long)D + seg);
        }
        asm volatile("cp.async.commit_group;" ::: "memory");
    }

    const int nsub = F / LF;
    const int nmy = (g < nsub) ? (nsub - 1 - g) / G + 1 : 0;
    const int T = nmy * 8;                           // D/LKC == 8 chunks

    auto load_A = [&](int t) {
        int i_sub = t >> 3, kc = t & 7, buf = t % 3;
        long f0 = (long)(g + i_sub * G) * LF;
        int row = tid >> 2;                          // 0..127
        int seg = (tid & 3) * 8;
        long gg = (fbase + f0 + row) * D + kc * LKC + seg;
        cp16(sbase + L_A_OFF + (uint32_t)buf * L_A_BUF +
                 (uint32_t)((row * LDA2 + seg) * 2),
             fv_h + gg);
        asm volatile("cp.async.commit_group;" ::: "memory");
    };

    if (T > 0) load_A(0);
    if (T > 1) load_A(1);

    int t = 0;
    for (int i = 0; i < nmy; ++i) {
        const int f0 = (g + i * G) * LF;

        // prefetch scatter indices for this subtile
        int hh[4], ww[4];
        #pragma unroll
        for (int mi = 0; mi < 2; ++mi) {
            #pragma unroll
            for (int half = 0; half < 2; ++half) {
                int row = warp_m + mi * 16 + half * 8 + (lane >> 2);
                long n = fbase + f0 + row;
                hh[mi * 2 + half] = fidx[3 * n + 1];
                ww[mi * 2 + half] = fidx[3 * n + 2];
            }
        }

        float c[2][5][4] = {};

        for (int kc = 0; kc < 8; ++kc, ++t) {
            if (t + 2 < T) {
                load_A(t + 2);
                asm volatile("cp.async.wait_group 2;" ::: "memory");
            } else if (t + 1 < T) {
                asm volatile("cp.async.wait_group 1;" ::: "memory");
            } else {
                asm volatile("cp.async.wait_group 0;" ::: "memory");
            }
            __syncthreads();

            const uint32_t as = sbase + L_A_OFF + (uint32_t)(t % 3) * L_A_BUF;

            #pragma unroll
            for (int kk = 0; kk < LKC; kk += 16) {
                uint32_t a[2][4];
                #pragma unroll
                for (int mi = 0; mi < 2; ++mi) {
                    int row = warp_m + mi * 16 + (lane & 15);
                    int col = kk + ((lane >> 4) << 3);
                    ldmatrix_x4(a[mi], as + (uint32_t)((row * LDA2 + col) * 2));
                }
                uint32_t bf[5][2];
                {
                    int col = kc * LKC + kk + ((lane >> 3) & 1) * 8;
                    int r1 = warp_n + ((lane & 16) >> 1) + (lane & 7);
                    uint32_t r[4];
                    ldmatrix_x4(r, sbase + L_B_OFF +
                                       (uint32_t)((r1 * LDB2 + col) * 2));
                    bf[0][0] = r[0]; bf[0][1] = r[1];
                    bf[1][0] = r[2]; bf[1][1] = r[3];
                    ldmatrix_x4(r, sbase + L_B_OFF +
                                       (uint32_t)(((r1 + 16) * LDB2 + col) * 2));
                    bf[2][0] = r[0]; bf[2][1] = r[1];
                    bf[3][0] = r[2]; bf[3][1] = r[3];
                    int r2 = warp_n + 32 + (lane & 7);
                    ldmatrix_x2(bf[4], sbase + L_B_OFF +
                                           (uint32_t)((r2 * LDB2 + col) * 2));
                }
                #pragma unroll
                for (int mi = 0; mi < 2; ++mi) {
                    #pragma unroll
                    for (int ni = 0; ni < 5; ++ni) {
                        mma_f16(c[mi][ni], a[mi], bf[ni]);
                    }
                }
            }
            __syncthreads();
        }

        // ---- epilogue for this subtile: lane-paired float4 atomics ----
        #pragma unroll
        for (int mi = 0; mi < 2; ++mi) {
            #pragma unroll
            for (int half = 0; half < 2; ++half) {
                int row = warp_m + mi * 16 + half * 8 + (lane >> 2);
                int f = f0 + row;
                bool ok = (f < F);
                long obase = (long)b * HWQ +
                             ((long)hh[mi * 2 + half] * Wd + ww[mi * 2 + half]) *
                                 (long)Q;
                #pragma unroll
                for (int ni = 0; ni < 5; ++ni) {
                    float v0 = c[mi][ni][half * 2 + 0];
                    float v1 = c[mi][ni][half * 2 + 1];
                    float p0 = __shfl_xor_sync(0xFFFFFFFFu, v0, 1);
                    float p1 = __shfl_xor_sync(0xFFFFFFFFu, v1, 1);
                    if (ok && (lane & 1) == 0) {
                        int q = q0 + warp_n + ni * 8 + 2 * (lane & 3);
                        if (q + 3 < Q) {
                            atomicAdd(reinterpret_cast<float4*>(out + obase + q),
                                      make_float4(v0, v1, p0, p1));
                        } else {
                            if (q     < Q) atomicAdd(out + obase + q,     v0);
                            if (q + 1 < Q) atomicAdd(out + obase + q + 1, v1);
                            if (q + 2 < Q) atomicAdd(out + obase + q + 2, p0);
                            if (q + 3 < Q) atomicAdd(out + obase + q + 3, p1);
                        }
                    }
                }
            }
        }
    }
}

// ---------------------------------------------------------------------------
static int isqrt_host(long v) {
    int r = (int)(sqrt((double)v) + 0.5);
    while ((long)r * r > v) --r;
    while ((long)(r + 1) * (r + 1) <= v) ++r;
    return r;
}

extern "C" void kernel_launch(void* const* d_in, const int* in_sizes, int n_in,
                              void* d_out, int out_size) {
    const float* queries = (const float*)d_in[0];
    const float* fv      = (const float*)d_in[1];
    const int*   fidx    = (const int*)d_in[2];

    bool scalars_present = (n_in >= 15 && in_sizes[5] == 1 && in_sizes[6] == 1);
    int wbase = scalars_present ? 7 : 5;
    const int* width_ptr = scalars_present ? (const int*)d_in[6] : nullptr;

    const float* Wl[4];
    const float* bl[4];
    for (int i = 0; i < 4; ++i) {
        Wl[i] = (const float*)d_in[wbase + 2 * i];
        bl[i] = (const float*)d_in[wbase + 2 * i + 1];
    }

    const int D  = in_sizes[wbase + 1];       // len(b0)
    const int Mq = in_sizes[0] / D;           // B*Q
    const int B  = in_sizes[3] - 1;
    const int Q  = Mq / B;
    const int NF = in_sizes[1] / D;           // B*F
    const int F  = NF / B;
    const long HWQ = (long)out_size / B;      // H*W*Q
    const int width_imm = isqrt_host(HWQ / Q);

    __half *fv_h = nullptr, *q_h = nullptr;
    __nv_bfloat16 *x0h = nullptr, *x0l = nullptr, *x1h = nullptr, *x1l = nullptr;
    __nv_bfloat16 *wh = nullptr, *wl = nullptr;
    cudaGetSymbolAddress((void**)&fv_h, g_fv_h);
    cudaGetSymbolAddress((void**)&q_h, g_q_h);
    cudaGetSymbolAddress((void**)&x0h, g_x0_hi);
    cudaGetSymbolAddress((void**)&x0l, g_x0_lo);
    cudaGetSymbolAddress((void**)&x1h, g_x1_hi);
    cudaGetSymbolAddress((void**)&x1l, g_x1_lo);
    cudaGetSymbolAddress((void**)&wh, g_w_hi);
    cudaGetSymbolAddress((void**)&wl, g_w_lo);

    static cudaStream_t side1 = nullptr;
    static cudaEvent_t ev_fork = nullptr, ev_j1 = nullptr;
    static bool attr_done = false;
    if (!side1) {
        cudaStreamCreateWithFlags(&side1, cudaStreamNonBlocking);
        cudaEventCreateWithFlags(&ev_fork, cudaEventDisableTiming);
        cudaEventCreateWithFlags(&ev_j1, cudaEventDisableTiming);
    }
    if (!attr_done) {
        cudaFuncSetAttribute(logits_mma_kernel,
                             cudaFuncAttributeMaxDynamicSharedMemorySize,
                             LOGITS_SMEM);
        cudaFuncSetAttribute(mlp_mma_kernel<1, 0>,
                             cudaFuncAttributeMaxDynamicSharedMemorySize,
                             MLP_SMEM);
        cudaFuncSetAttribute(mlp_mma_kernel<0, 1>,
                             cudaFuncAttributeMaxDynamicSharedMemorySize,
                             MLP_SMEM);
        attr_done = true;
    }

    // ---- fork: side1 runs prep (fv convert + zero out) ----
    cudaEventRecord(ev_fork, 0);
    cudaStreamWaitEvent(side1, ev_fork, 0);
    {
        long n4_fv = (long)NF * D / 4;
        long n4_out = (long)out_size / 4;
        long total = n4_fv + n4_out;
        prep_kernel<<<(int)DIV_UP(total, 256L), 256, 0, side1>>>(
            fv, fv_h, (float*)d_out, n4_fv, n4_out);
    }

    // main: weight split, query split, 4 tensor-core MLP layers
    {
        long w4 = (long)D * D / 4;
        convert_split4_kernel<<<(int)DIV_UP(4 * w4, 256L), 256>>>(
            Wl[0], Wl[1], Wl[2], Wl[3], wh, wl, w4);
    }
    {
        long n4 = (long)Mq * D / 4;
        convert_split_kernel<<<(int)DIV_UP(n4, 256L), 256>>>(queries, x0h, x0l, n4);
    }
    {
        dim3 grid(D / 64, DIV_UP(Mq, 64));
        long wsz = (long)D * D;
        mlp_mma_kernel<1, 0><<<grid, 128, MLP_SMEM>>>(
            x0h, x0l, wh + 0 * wsz, wl + 0 * wsz, bl[0], x1h, x1l, nullptr,
            Mq, D, D);
        mlp_mma_kernel<1, 0><<<grid, 128, MLP_SMEM>>>(
            x1h, x1l, wh + 1 * wsz, wl + 1 * wsz, bl[1], x0h, x0l, nullptr,
            Mq, D, D);
        mlp_mma_kernel<1, 0><<<grid, 128, MLP_SMEM>>>(
            x0h, x0l, wh + 2 * wsz, wl + 2 * wsz, bl[2], x1h, x1l, nullptr,
            Mq, D, D);
        mlp_mma_kernel<0, 1><<<grid, 128, MLP_SMEM>>>(
            x1h, x1l, wh + 3 * wsz, wl + 3 * wsz, bl[3], nullptr, nullptr, q_h,
            Mq, D, D);
    }

    // ---- join ----
    cudaEventRecord(ev_j1, side1);
    cudaStreamWaitEvent(0, ev_j1, 0);

    // Logits GEMM v3.1 (B-persistent, single uniform wave) + scatter-add
    {
        int nsub = F / LF;
        int G = nsub / 8;                // 16 for F=16384: 8 subtiles per CTA
        if (G < 1) G = 1;
        dim3 grid(DIV_UP(Q, LQT), G, B);
        logits_mma_kernel<<<grid, 512, LOGITS_SMEM>>>(fv_h, q_h, fidx,
                                                      (float*)d_out,
                                                      width_ptr, width_imm,
                                                      F, Q, D, HWQ);
    }
}

// round 16
// speedup vs baseline: 1.3731x; 1.0932x over previous
#include <cuda_runtime.h>
#include <cuda_bf16.h>
#include <cuda_fp16.h>
#include <cstdint>
#include <cmath>

#define DIV_UP(a, b) (((a) + (b) - 1) / (b))

// Scratch (static device allocations — the only legal kind here)
__device__ __align__(16) __half g_fv_h[1 << 24];           // 33.5 MB fp16 fv
__device__ __align__(16) __half g_q_h[1 << 19];            // fp16 q (MLP out)
__device__ __align__(16) __nv_bfloat16 g_x0_hi[1 << 19];   // MLP act planes
__device__ __align__(16) __nv_bfloat16 g_x0_lo[1 << 19];
__device__ __align__(16) __nv_bfloat16 g_x1_hi[1 << 19];
__device__ __align__(16) __nv_bfloat16 g_x1_lo[1 << 19];
__device__ __align__(16) __nv_bfloat16 g_w_hi[1 << 18];    // 4 weight mats
__device__ __align__(16) __nv_bfloat16 g_w_lo[1 << 18];

// ============================================================================
// helpers
// ============================================================================
__device__ __forceinline__ uint32_t smem_to_u32(const void* smem_ptr) {
    uint32_t addr;
    asm("{ .reg .u64 tmp; cvta.to.shared.u64 tmp, %1; cvt.u32.u64 %0, tmp; }"
        : "=r"(addr) : "l"(smem_ptr));
    return addr;
}

__device__ __forceinline__ void ldmatrix_x4(uint32_t* r, uint32_t addr) {
    asm volatile("ldmatrix.sync.aligned.m8n8.x4.shared.b16 {%0,%1,%2,%3}, [%4];"
                 : "=r"(r[0]), "=r"(r[1]), "=r"(r[2]), "=r"(r[3]) : "r"(addr));
}

__device__ __forceinline__ void ldmatrix_x2(uint32_t* r, uint32_t addr) {
    asm volatile("ldmatrix.sync.aligned.m8n8.x2.shared.b16 {%0,%1}, [%2];"
                 : "=r"(r[0]), "=r"(r[1]) : "r"(addr));
}

// D += A(f16) * B(f16)^T, m16n8k16, fp32 accumulate
__device__ __forceinline__ void mma_f16(float* c, const uint32_t* a,
                                        const uint32_t* b) {
    asm volatile(
        "mma.sync.aligned.m16n8k16.row.col.f32.f16.f16.f32 "
        "{%0,%1,%2,%3}, {%4,%5,%6,%7}, {%8,%9}, {%0,%1,%2,%3};"
        : "+f"(c[0]), "+f"(c[1]), "+f"(c[2]), "+f"(c[3])
        : "r"(a[0]), "r"(a[1]), "r"(a[2]), "r"(a[3]), "r"(b[0]), "r"(b[1]));
}

// D += A(bf16) * B(bf16)^T, m16n8k16, fp32 accumulate
__device__ __forceinline__ void mma_bf16(float* c, const uint32_t* a,
                                         const uint32_t* b) {
    asm volatile(
        "mma.sync.aligned.m16n8k16.row.col.f32.bf16.bf16.f32 "
        "{%0,%1,%2,%3}, {%4,%5,%6,%7}, {%8,%9}, {%0,%1,%2,%3};"
        : "+f"(c[0]), "+f"(c[1]), "+f"(c[2]), "+f"(c[3])
        : "r"(a[0]), "r"(a[1]), "r"(a[2]), "r"(a[3]), "r"(b[0]), "r"(b[1]));
}

__device__ __forceinline__ void cp16(uint32_t smem, const void* g) {
    asm volatile("cp.async.cg.shared.global [%0], [%1], 16;"
                 :: "r"(smem), "l"(g));
}

// split fp32 pair into packed bf16x2 hi and lo planes
__device__ __forceinline__ void split2(float x, float y, uint32_t& hi, uint32_t& lo) {
    __nv_bfloat16 hx = __float2bfloat16(x);
    __nv_bfloat16 hy = __float2bfloat16(y);
    __nv_bfloat16 lx = __float2bfloat16(x - __bfloat162float(hx));
    __nv_bfloat16 ly = __float2bfloat16(y - __bfloat162float(hy));
    hi = (uint32_t)__bfloat16_as_ushort(hx) | ((uint32_t)__bfloat16_as_ushort(hy) << 16);
    lo = (uint32_t)__bfloat16_as_ushort(lx) | ((uint32_t)__bfloat16_as_ushort(ly) << 16);
}

// ============================================================================
// conversion kernels
// ============================================================================
__global__ void __launch_bounds__(256)
convert_half_kernel(const float* __restrict__ in, __half* __restrict__ outp,
                    long n4) {
    long i = (long)blockIdx.x * blockDim.x + threadIdx.x;
    if (i >= n4) return;
    float4 v = reinterpret_cast<const float4*>(in)[i];
    reinterpret_cast<__half2*>(outp)[2 * i + 0] = __floats2half2_rn(v.x, v.y);
    reinterpret_cast<__half2*>(outp)[2 * i + 1] = __floats2half2_rn(v.z, v.w);
}

__global__ void __launch_bounds__(256)
convert_split_kernel(const float* __restrict__ in,
                     __nv_bfloat16* __restrict__ hi,
                     __nv_bfloat16* __restrict__ lo, long n4) {
    long i = (long)blockIdx.x * blockDim.x + threadIdx.x;
    if (i >= n4) return;
    float4 v = reinterpret_cast<const float4*>(in)[i];
    uint32_t h0, l0, h1, l1;
    split2(v.x, v.y, h0, l0);
    split2(v.z, v.w, h1, l1);
    reinterpret_cast<uint2*>(hi)[i] = make_uint2(h0, h1);
    reinterpret_cast<uint2*>(lo)[i] = make_uint2(l0, l1);
}

__global__ void __launch_bounds__(256)
convert_split4_kernel(const float* __restrict__ w0, const float* __restrict__ w1,
                      const float* __restrict__ w2, const float* __restrict__ w3,
                      __nv_bfloat16* __restrict__ hi,
                      __nv_bfloat16* __restrict__ lo, long w4) {
    long i = (long)blockIdx.x * blockDim.x + threadIdx.x;
    if (i >= 4 * w4) return;
    int m = (int)(i / w4);
    long j = i - (long)m * w4;
    const float* src = (m == 0) ? w0 : (m == 1) ? w1 : (m == 2) ? w2 : w3;
    float4 v = reinterpret_cast<const float4*>(src)[j];
    uint32_t h0, l0, h1, l1;
    split2(v.x, v.y, h0, l0);
    split2(v.z, v.w, h1, l1);
    reinterpret_cast<uint2*>(hi)[i] = make_uint2(h0, h1);
    reinterpret_cast<uint2*>(lo)[i] = make_uint2(l0, l1);
}

// ============================================================================
// MLP layer v3: FULL-K single-load design. CTA = 32m x 32n, K=256 entirely in
// smem (A 32xK hi/lo + W 32xK hi/lo = 66 KB), ONE cp.async burst, ONE sync,
// straight-line compute. 4 warps, warp tile 32m x 8n. Grid 8 x 38 = 304.
// LAST=1: writes fp16 q_h (no relu); else writes bf16 hi/lo act planes.
// ============================================================================
constexpr int MK    = 256;                  // full K
constexpr int MLDSB = (MK + 8) * 2;         // row stride bytes (528, 16B mult)
constexpr int MT_A_HI = 0;
constexpr int MT_A_LO = MT_A_HI + 32 * MLDSB;   // 16896
constexpr int MT_W_HI = MT_A_LO + 32 * MLDSB;   // 33792
constexpr int MT_W_LO = MT_W_HI + 32 * MLDSB;   // 50688
constexpr int MLP_SMEM = MT_W_LO + 32 * MLDSB;  // 67584

template <int RELU, int LAST>
__global__ void __launch_bounds__(128, 2)
mlp_mma_kernel(const __nv_bfloat16* __restrict__ x_hi,
               const __nv_bfloat16* __restrict__ x_lo,
               const __nv_bfloat16* __restrict__ w_hi,
               const __nv_bfloat16* __restrict__ w_lo,
               const float* __restrict__ bias,
               __nv_bfloat16* __restrict__ y_hi,
               __nv_bfloat16* __restrict__ y_lo,
               __half* __restrict__ yh,
               int M, int K, int N) {
    extern __shared__ __align__(16) char smem[];
    const uint32_t sbase = smem_to_u32(smem);

    const int tid  = threadIdx.x;
    const int wid  = tid >> 5;
    const int lane = tid & 31;
    const int n0 = blockIdx.x * 32;
    const int m0 = blockIdx.y * 32;

    // ---- single load phase: 32 ops/row-plane, 4096 cp.async total ----
    {
        // each thread: 32 ops. idx -> plane(4) x row(32) x seg(8 of 32B? no:
        // 32 segs of 16B per row). Layout: i in [0,4096): plane=i>>10,
        // rem=i&1023, row=rem>>5, seg=rem&31.
        #pragma unroll
        for (int u = 0; u < 32; ++u) {
            int i = tid + u * 128;
            int plane = i >> 10;
            int rem = i & 1023;
            int row = rem >> 5;
            int seg = rem & 31;
            uint32_t soff = (uint32_t)(plane * (32 * MLDSB) + row * MLDSB + seg * 16);
            const __nv_bfloat16* src;
            long gofs;
            if (plane < 2) {
                int m = m0 + row; if (m >= M) m = M - 1;
                gofs = (long)m * K + seg * 8;
                src = (plane == 0) ? x_hi : x_lo;
            } else {
                gofs = (long)(n0 + row) * K + seg * 8;
                src = (plane == 2) ? w_hi : w_lo;
            }
            cp16(sbase + soff, src + gofs);
        }
        asm volatile("cp.async.commit_group;" ::: "memory");
        asm volatile("cp.async.wait_group 0;" ::: "memory");
        __syncthreads();
    }

    const uint32_t ah_s = sbase + MT_A_HI;
    const uint32_t al_s = sbase + MT_A_LO;
    const uint32_t wh_s = sbase + MT_W_HI;
    const uint32_t wl_s = sbase + MT_W_LO;

    float c[2][4] = {};   // warp tile 32m x 8n: 2 m-frags x 4 regs

    #pragma unroll
    for (int kk = 0; kk < MK; kk += 16) {
        uint32_t ah[2][4], al[2][4];
        #pragma unroll
        for (int mi = 0; mi < 2; ++mi) {
            int row = mi * 16 + (lane & 15);
            int col = kk + ((lane >> 4) << 3);
            uint32_t addr = (uint32_t)(row * MLDSB + col * 2);
            ldmatrix_x4(ah[mi], ah_s + addr);
            ldmatrix_x4(al[mi], al_s + addr);
        }
        uint32_t bh[2], bl[2];
        {
            int row = wid * 8 + (lane & 7);
            int col = kk + ((lane >> 3) & 1) * 8;   // lanes 8-15 pick k+8
            uint32_t addr = (uint32_t)(row * MLDSB + col * 2);
            ldmatrix_x2(bh, wh_s + addr);
            ldmatrix_x2(bl, wl_s + addr);
        }
        #pragma unroll
        for (int mi = 0; mi < 2; ++mi) {
            mma_bf16(c[mi], ah[mi], bh);
            mma_bf16(c[mi], ah[mi], bl);
            mma_bf16(c[mi], al[mi], bh);
        }
    }

    // ---- epilogue ----
    #pragma unroll
    for (int mi = 0; mi < 2; ++mi) {
        #pragma unroll
        for (int half = 0; half < 2; ++half) {
            int m = m0 + mi * 16 + half * 8 + (lane >> 2);
            if (m >= M) continue;
            int n = n0 + wid * 8 + 2 * (lane & 3);
            float v0 = c[mi][half * 2 + 0] + bias[n];
            float v1 = c[mi][half * 2 + 1] + bias[n + 1];
            if (LAST) {
                *reinterpret_cast<__half2*>(yh + (long)m * N + n) =
                    __floats2half2_rn(v0, v1);
            } else {
                if (RELU) { v0 = fmaxf(v0, 0.f); v1 = fmaxf(v1, 0.f); }
                uint32_t h, l;
                split2(v0, v1, h, l);
                long o = ((long)m * N + n) >> 1;
                reinterpret_cast<uint32_t*>(y_hi)[o] = h;
                reinterpret_cast<uint32_t*>(y_lo)[o] = l;
            }
        }
    }
}

// ============================================================================
// Logits GEMM v3.2: R13 structure (B-persistent, triple-buffered A, G=16
// uniform wave) with ONE barrier per chunk (load issued post-sync; buffer
// (t+2)%3 == (t-1)%3 is idle once all threads passed sync(t)).
// 512 threads, 16 warps 4m x 4n, warp tile 32x40.
// ============================================================================
constexpr int LQT  = 160;
constexpr int LF   = 128;
constexpr int LKC  = 32;
constexpr int LDA2 = LKC + 8;    // A fp16 stride (40)
constexpr int LDB2 = 256 + 8;    // B fp16 stride (264), D=256
constexpr int L_B_OFF  = 0;
constexpr int L_B_SZ   = LQT * LDB2 * 2;             // 84480
constexpr int L_A_OFF  = L_B_SZ;
constexpr int L_A_BUF  = LF * LDA2 * 2;              // 10240
constexpr int LOGITS_SMEM = L_A_OFF + 3 * L_A_BUF;   // 115200

__global__ void __launch_bounds__(512, 1)
logits_mma_kernel(const __half* __restrict__ fv_h,   // [B*F, D] fp16
                  const __half* __restrict__ q_h,    // [B*Q, D] fp16
                  const int* __restrict__ fidx,      // [B*F, 3]
                  float* __restrict__ out,
                  const int* __restrict__ width_ptr, int width_imm,
                  int F, int Q, int D, long HWQ) {
    extern __shared__ __align__(16) char smem[];
    const uint32_t sbase = smem_to_u32(smem);

    const int tid  = threadIdx.x;
    const int wid  = tid >> 5;
    const int lane = tid & 31;
    const int qt = blockIdx.x;
    const int g  = blockIdx.y;
    const int G  = gridDim.y;
    const int b  = blockIdx.z;
    const int q0 = qt * LQT;

    const int warp_m = (wid & 3) * 32;       // 4 m-warps x 32 rows
    const int warp_n = (wid >> 2) * 40;      // 4 n-warps x 40 cols

    const long fbase = (long)b * F;
    const long brow0 = (long)b * Q;
    const int Wd = width_ptr ? *width_ptr : width_imm;

    // ---- load persistent B tile: 160 q-rows x full K (clamped) ----
    {
        const int kq = D >> 3;                       // 16B ops per row (32)
        for (int i = tid; i < LQT * kq; i += 512) {
            int row = i / kq;
            int seg = (i - row * kq) * 8;
            int q = q0 + row;
            if (q >= Q) q = Q - 1;                   // masked in epilogue
            cp16(sbase + L_B_OFF + (uint32_t)((row * LDB2 + seg) * 2),
                 q_h + (brow0 + q) * (long)D + seg);
        }
        asm volatile("cp.async.commit_group;" ::: "memory");
    }

    const int nsub = F / LF;
    const int nmy = (g < nsub) ? (nsub - 1 - g) / G + 1 : 0;
    const int T = nmy * 8;                           // D/LKC == 8 chunks

    auto load_A = [&](int t) {
        int i_sub = t >> 3, kc = t & 7, buf = t % 3;
        long f0 = (long)(g + i_sub * G) * LF;
        int row = tid >> 2;                          // 0..127
        int seg = (tid & 3) * 8;
        long gg = (fbase + f0 + row) * D + kc * LKC + seg;
        cp16(sbase + L_A_OFF + (uint32_t)buf * L_A_BUF +
                 (uint32_t)((row * LDA2 + seg) * 2),
             fv_h + gg);
        asm volatile("cp.async.commit_group;" ::: "memory");
    };

    if (T > 0) load_A(0);
    if (T > 1) load_A(1);

    int t = 0;
    for (int i = 0; i < nmy; ++i) {
        const int f0 = (g + i * G) * LF;

        // prefetch scatter indices for this subtile
        int hh[4], ww[4];
        #pragma unroll
        for (int mi = 0; mi < 2; ++mi) {
            #pragma unroll
            for (int half = 0; half < 2; ++half) {
                int row = warp_m + mi * 16 + half * 8 + (lane >> 2);
                long n = fbase + f0 + row;
                hh[mi * 2 + half] = fidx[3 * n + 1];
                ww[mi * 2 + half] = fidx[3 * n + 2];
            }
        }

        float c[2][5][4] = {};

        for (int kc = 0; kc < 8; ++kc, ++t) {
            // wait for A(t); A(t+1) may remain in flight
            if (t + 1 < T) {
                asm volatile("cp.async.wait_group 1;" ::: "memory");
            } else {
                asm volatile("cp.async.wait_group 0;" ::: "memory");
            }
            __syncthreads();                          // single barrier per chunk
            if (t + 2 < T) load_A(t + 2);             // safe: buf (t-1)%3 idle

            const uint32_t as = sbase + L_A_OFF + (uint32_t)(t % 3) * L_A_BUF;

            #pragma unroll
            for (int kk = 0; kk < LKC; kk += 16) {
                uint32_t a[2][4];
                #pragma unroll
                for (int mi = 0; mi < 2; ++mi) {
                    int row = warp_m + mi * 16 + (lane & 15);
                    int col = kk + ((lane >> 4) << 3);
                    ldmatrix_x4(a[mi], as + (uint32_t)((row * LDA2 + col) * 2));
                }
                uint32_t bf[5][2];
                {
                    int col = kc * LKC + kk + ((lane >> 3) & 1) * 8;
                    int r1 = warp_n + ((lane & 16) >> 1) + (lane & 7);
                    uint32_t r[4];
                    ldmatrix_x4(r, sbase + L_B_OFF +
                                       (uint32_t)((r1 * LDB2 + col) * 2));
                    bf[0][0] = r[0]; bf[0][1] = r[1];
                    bf[1][0] = r[2]; bf[1][1] = r[3];
                    ldmatrix_x4(r, sbase + L_B_OFF +
                                       (uint32_t)(((r1 + 16) * LDB2 + col) * 2));
                    bf[2][0] = r[0]; bf[2][1] = r[1];
                    bf[3][0] = r[2]; bf[3][1] = r[3];
                    int r2 = warp_n + 32 + (lane & 7);
                    ldmatrix_x2(bf[4], sbase + L_B_OFF +
                                           (uint32_t)((r2 * LDB2 + col) * 2));
                }
                #pragma unroll
                for (int mi = 0; mi < 2; ++mi) {
                    #pragma unroll
                    for (int ni = 0; ni < 5; ++ni) {
                        mma_f16(c[mi][ni], a[mi], bf[ni]);
                    }
                }
            }
        }

        // ---- epilogue for this subtile: lane-paired float4 atomics ----
        #pragma unroll
        for (int mi = 0; mi < 2; ++mi) {
            #pragma unroll
            for (int half = 0; half < 2; ++half) {
                int row = warp_m + mi * 16 + half * 8 + (lane >> 2);
                int f = f0 + row;
                bool ok = (f < F);
                long obase = (long)b * HWQ +
                             ((long)hh[mi * 2 + half] * Wd + ww[mi * 2 + half]) *
                                 (long)Q;
                #pragma unroll
                for (int ni = 0; ni < 5; ++ni) {
                    float v0 = c[mi][ni][half * 2 + 0];
                    float v1 = c[mi][ni][half * 2 + 1];
                    float p0 = __shfl_xor_sync(0xFFFFFFFFu, v0, 1);
                    float p1 = __shfl_xor_sync(0xFFFFFFFFu, v1, 1);
                    if (ok && (lane & 1) == 0) {
                        int q = q0 + warp_n + ni * 8 + 2 * (lane & 3);
                        if (q + 3 < Q) {
                            atomicAdd(reinterpret_cast<float4*>(out + obase + q),
                                      make_float4(v0, v1, p0, p1));
                        } else {
                            if (q     < Q) atomicAdd(out + obase + q,     v0);
                            if (q + 1 < Q) atomicAdd(out + obase + q + 1, v1);
                            if (q + 2 < Q) atomicAdd(out + obase + q + 2, p0);
                            if (q + 3 < Q) atomicAdd(out + obase + q + 3, p1);
                        }
                    }
                }
            }
        }
    }
}

// ---------------------------------------------------------------------------
static int isqrt_host(long v) {
    int r = (int)(sqrt((double)v) + 0.5);
    while ((long)r * r > v) --r;
    while ((long)(r + 1) * (r + 1) <= v) ++r;
    return r;
}

extern "C" void kernel_launch(void* const* d_in, const int* in_sizes, int n_in,
                              void* d_out, int out_size) {
    const float* queries = (const float*)d_in[0];
    const float* fv      = (const float*)d_in[1];
    const int*   fidx    = (const int*)d_in[2];

    bool scalars_present = (n_in >= 15 && in_sizes[5] == 1 && in_sizes[6] == 1);
    int wbase = scalars_present ? 7 : 5;
    const int* width_ptr = scalars_present ? (const int*)d_in[6] : nullptr;

    const float* Wl[4];
    const float* bl[4];
    for (int i = 0; i < 4; ++i) {
        Wl[i] = (const float*)d_in[wbase + 2 * i];
        bl[i] = (const float*)d_in[wbase + 2 * i + 1];
    }

    const int D  = in_sizes[wbase + 1];       // len(b0)
    const int Mq = in_sizes[0] / D;           // B*Q
    const int B  = in_sizes[3] - 1;
    const int Q  = Mq / B;
    const int NF = in_sizes[1] / D;           // B*F
    const int F  = NF / B;
    const long HWQ = (long)out_size / B;      // H*W*Q
    const int width_imm = isqrt_host(HWQ / Q);

    __half *fv_h = nullptr, *q_h = nullptr;
    __nv_bfloat16 *x0h = nullptr, *x0l = nullptr, *x1h = nullptr, *x1l = nullptr;
    __nv_bfloat16 *wh = nullptr, *wl = nullptr;
    cudaGetSymbolAddress((void**)&fv_h, g_fv_h);
    cudaGetSymbolAddress((void**)&q_h, g_q_h);
    cudaGetSymbolAddress((void**)&x0h, g_x0_hi);
    cudaGetSymbolAddress((void**)&x0l, g_x0_lo);
    cudaGetSymbolAddress((void**)&x1h, g_x1_hi);
    cudaGetSymbolAddress((void**)&x1l, g_x1_lo);
    cudaGetSymbolAddress((void**)&wh, g_w_hi);
    cudaGetSymbolAddress((void**)&wl, g_w_lo);

    static cudaStream_t side1 = nullptr, side2 = nullptr;
    static cudaEvent_t ev_fork = nullptr, ev_j1 = nullptr, ev_j2 = nullptr;
    static bool attr_done = false;
    if (!side1) {
        cudaStreamCreateWithFlags(&side1, cudaStreamNonBlocking);
        cudaStreamCreateWithFlags(&side2, cudaStreamNonBlocking);
        cudaEventCreateWithFlags(&ev_fork, cudaEventDisableTiming);
        cudaEventCreateWithFlags(&ev_j1, cudaEventDisableTiming);
        cudaEventCreateWithFlags(&ev_j2, cudaEventDisableTiming);
    }
    if (!attr_done) {
        cudaFuncSetAttribute(logits_mma_kernel,
                             cudaFuncAttributeMaxDynamicSharedMemorySize,
                             LOGITS_SMEM);
        cudaFuncSetAttribute(mlp_mma_kernel<1, 0>,
                             cudaFuncAttributeMaxDynamicSharedMemorySize,
                             MLP_SMEM);
        cudaFuncSetAttribute(mlp_mma_kernel<0, 1>,
                             cudaFuncAttributeMaxDynamicSharedMemorySize,
                             MLP_SMEM);
        attr_done = true;
    }

    // ---- fork: side1 converts fv -> fp16; side2 zeroes output ----
    cudaEventRecord(ev_fork, 0);
    cudaStreamWaitEvent(side1, ev_fork, 0);
    cudaStreamWaitEvent(side2, ev_fork, 0);
    {
        long n4 = (long)NF * D / 4;
        convert_half_kernel<<<(int)DIV_UP(n4, 256L), 256, 0, side1>>>(fv, fv_h, n4);
    }
    cudaMemsetAsync(d_out, 0, (size_t)out_size * sizeof(float), side2);

    // main: weight split, query split, 4 full-K tensor-core MLP layers
    {
        long w4 = (long)D * D / 4;
        convert_split4_kernel<<<(int)DIV_UP(4 * w4, 256L), 256>>>(
            Wl[0], Wl[1], Wl[2], Wl[3], wh, wl, w4);
    }
    {
        long n4 = (long)Mq * D / 4;
        convert_split_kernel<<<(int)DIV_UP(n4, 256L), 256>>>(queries, x0h, x0l, n4);
    }
    {
        dim3 grid(D / 32, DIV_UP(Mq, 32));
        long wsz = (long)D * D;
        mlp_mma_kernel<1, 0><<<grid, 128, MLP_SMEM>>>(
            x0h, x0l, wh + 0 * wsz, wl + 0 * wsz, bl[0], x1h, x1l, nullptr,
            Mq, D, D);
        mlp_mma_kernel<1, 0><<<grid, 128, MLP_SMEM>>>(
            x1h, x1l, wh + 1 * wsz, wl + 1 * wsz, bl[1], x0h, x0l, nullptr,
            Mq, D, D);
        mlp_mma_kernel<1, 0><<<grid, 128, MLP_SMEM>>>(
            x0h, x0l, wh + 2 * wsz, wl + 2 * wsz, bl[2], x1h, x1l, nullptr,
            Mq, D, D);
        mlp_mma_kernel<0, 1><<<grid, 128, MLP_SMEM>>>(
            x1h, x1l, wh + 3 * wsz, wl + 3 * wsz, bl[3], nullptr, nullptr, q_h,
            Mq, D, D);
    }

    // ---- join ----
    cudaEventRecord(ev_j1, side1);
    cudaEventRecord(ev_j2, side2);
    cudaStreamWaitEvent(0, ev_j1, 0);
    cudaStreamWaitEvent(0, ev_j2, 0);

    // Logits GEMM v3.2 (single-barrier chunks) + scatter-add
    {
        int nsub = F / LF;
        int G = nsub / 8;                // 16 for F=16384: 8 subtiles per CTA
        if (G < 1) G = 1;
        dim3 grid(DIV_UP(Q, LQT), G, B);
        logits_mma_kernel<<<grid, 512, LOGITS_SMEM>>>(fv_h, q_h, fidx,
                                                      (float*)d_out,
                                                      width_ptr, width_imm,
                                                      F, Q, D, HWQ);
    }
}

// round 17
// speedup vs baseline: 1.4454x; 1.0526x over previous
#include <cuda_runtime.h>
#include <cuda_bf16.h>
#include <cuda_fp16.h>
#include <cstdint>
#include <cmath>

#define DIV_UP(a, b) (((a) + (b) - 1) / (b))

// Scratch (static device allocations — the only legal kind here)
__device__ __align__(16) __half g_fv_h[1 << 24];           // 33.5 MB fp16 fv
__device__ __align__(16) __half g_q_h[1 << 19];            // fp16 q (MLP out)
__device__ __align__(16) __nv_bfloat16 g_x0_hi[1 << 19];   // MLP act planes
__device__ __align__(16) __nv_bfloat16 g_x0_lo[1 << 19];
__device__ __align__(16) __nv_bfloat16 g_x1_hi[1 << 19];
__device__ __align__(16) __nv_bfloat16 g_x1_lo[1 << 19];
__device__ __align__(16) __nv_bfloat16 g_w_hi[1 << 18];    // 4 weight mats
__device__ __align__(16) __nv_bfloat16 g_w_lo[1 << 18];

// ============================================================================
// helpers
// ============================================================================
__device__ __forceinline__ uint32_t smem_to_u32(const void* smem_ptr) {
    uint32_t addr;
    asm("{ .reg .u64 tmp; cvta.to.shared.u64 tmp, %1; cvt.u32.u64 %0, tmp; }"
        : "=r"(addr) : "l"(smem_ptr));
    return addr;
}

__device__ __forceinline__ void ldmatrix_x4(uint32_t* r, uint32_t addr) {
    asm volatile("ldmatrix.sync.aligned.m8n8.x4.shared.b16 {%0,%1,%2,%3}, [%4];"
                 : "=r"(r[0]), "=r"(r[1]), "=r"(r[2]), "=r"(r[3]) : "r"(addr));
}

__device__ __forceinline__ void ldmatrix_x2(uint32_t* r, uint32_t addr) {
    asm volatile("ldmatrix.sync.aligned.m8n8.x2.shared.b16 {%0,%1}, [%2];"
                 : "=r"(r[0]), "=r"(r[1]) : "r"(addr));
}

// D += A(f16) * B(f16)^T, m16n8k16, fp32 accumulate
__device__ __forceinline__ void mma_f16(float* c, const uint32_t* a,
                                        const uint32_t* b) {
    asm volatile(
        "mma.sync.aligned.m16n8k16.row.col.f32.f16.f16.f32 "
        "{%0,%1,%2,%3}, {%4,%5,%6,%7}, {%8,%9}, {%0,%1,%2,%3};"
        : "+f"(c[0]), "+f"(c[1]), "+f"(c[2]), "+f"(c[3])
        : "r"(a[0]), "r"(a[1]), "r"(a[2]), "r"(a[3]), "r"(b[0]), "r"(b[1]));
}

// D += A(bf16) * B(bf16)^T, m16n8k16, fp32 accumulate
__device__ __forceinline__ void mma_bf16(float* c, const uint32_t* a,
                                         const uint32_t* b) {
    asm volatile(
        "mma.sync.aligned.m16n8k16.row.col.f32.bf16.bf16.f32 "
        "{%0,%1,%2,%3}, {%4,%5,%6,%7}, {%8,%9}, {%0,%1,%2,%3};"
        : "+f"(c[0]), "+f"(c[1]), "+f"(c[2]), "+f"(c[3])
        : "r"(a[0]), "r"(a[1]), "r"(a[2]), "r"(a[3]), "r"(b[0]), "r"(b[1]));
}

__device__ __forceinline__ void cp16(uint32_t smem, const void* g) {
    asm volatile("cp.async.cg.shared.global [%0], [%1], 16;"
                 :: "r"(smem), "l"(g));
}

// split fp32 pair into packed bf16x2 hi and lo planes
__device__ __forceinline__ void split2(float x, float y, uint32_t& hi, uint32_t& lo) {
    __nv_bfloat16 hx = __float2bfloat16(x);
    __nv_bfloat16 hy = __float2bfloat16(y);
    __nv_bfloat16 lx = __float2bfloat16(x - __bfloat162float(hx));
    __nv_bfloat16 ly = __float2bfloat16(y - __bfloat162float(hy));
    hi = (uint32_t)__bfloat16_as_ushort(hx) | ((uint32_t)__bfloat16_as_ushort(hy) << 16);
    lo = (uint32_t)__bfloat16_as_ushort(lx) | ((uint32_t)__bfloat16_as_ushort(ly) << 16);
}

// ============================================================================
// conversion kernels
// ============================================================================
__global__ void __launch_bounds__(256)
convert_half_kernel(const float* __restrict__ in, __half* __restrict__ outp,
                    long n4) {
    long i = (long)blockIdx.x * blockDim.x + threadIdx.x;
    if (i >= n4) return;
    float4 v = reinterpret_cast<const float4*>(in)[i];
    reinterpret_cast<__half2*>(outp)[2 * i + 0] = __floats2half2_rn(v.x, v.y);
    reinterpret_cast<__half2*>(outp)[2 * i + 1] = __floats2half2_rn(v.z, v.w);
}

__global__ void __launch_bounds__(256)
convert_split_kernel(const float* __restrict__ in,
                     __nv_bfloat16* __restrict__ hi,
                     __nv_bfloat16* __restrict__ lo, long n4) {
    long i = (long)blockIdx.x * blockDim.x + threadIdx.x;
    if (i >= n4) return;
    float4 v = reinterpret_cast<const float4*>(in)[i];
    uint32_t h0, l0, h1, l1;
    split2(v.x, v.y, h0, l0);
    split2(v.z, v.w, h1, l1);
    reinterpret_cast<uint2*>(hi)[i] = make_uint2(h0, h1);
    reinterpret_cast<uint2*>(lo)[i] = make_uint2(l0, l1);
}

__global__ void __launch_bounds__(256)
convert_split4_kernel(const float* __restrict__ w0, const float* __restrict__ w1,
                      const float* __restrict__ w2, const float* __restrict__ w3,
                      __nv_bfloat16* __restrict__ hi,
                      __nv_bfloat16* __restrict__ lo, long w4) {
    long i = (long)blockIdx.x * blockDim.x + threadIdx.x;
    if (i >= 4 * w4) return;
    int m = (int)(i / w4);
    long j = i - (long)m * w4;
    const float* src = (m == 0) ? w0 : (m == 1) ? w1 : (m == 2) ? w2 : w3;
    float4 v = reinterpret_cast<const float4*>(src)[j];
    uint32_t h0, l0, h1, l1;
    split2(v.x, v.y, h0, l0);
    split2(v.z, v.w, h1, l1);
    reinterpret_cast<uint2*>(hi)[i] = make_uint2(h0, h1);
    reinterpret_cast<uint2*>(lo)[i] = make_uint2(l0, l1);
}

// ============================================================================
// MLP layer v3: FULL-K single-load design. CTA = 32m x 32n, K=256 entirely in
// smem, ONE cp.async burst, ONE sync, straight-line compute. 3 CTAs/SM.
// LAST=1: writes fp16 q_h (no relu); else writes bf16 hi/lo act planes.
// ============================================================================
constexpr int MK    = 256;                  // full K
constexpr int MLDSB = (MK + 8) * 2;         // row stride bytes (528, 16B mult)
constexpr int MT_A_HI = 0;
constexpr int MT_A_LO = MT_A_HI + 32 * MLDSB;   // 16896
constexpr int MT_W_HI = MT_A_LO + 32 * MLDSB;   // 33792
constexpr int MT_W_LO = MT_W_HI + 32 * MLDSB;   // 50688
constexpr int MLP_SMEM = MT_W_LO + 32 * MLDSB;  // 67584 (x3 CTA = 203 KB)

template <int RELU, int LAST>
__global__ void __launch_bounds__(128, 3)
mlp_mma_kernel(const __nv_bfloat16* __restrict__ x_hi,
               const __nv_bfloat16* __restrict__ x_lo,
               const __nv_bfloat16* __restrict__ w_hi,
               const __nv_bfloat16* __restrict__ w_lo,
               const float* __restrict__ bias,
               __nv_bfloat16* __restrict__ y_hi,
               __nv_bfloat16* __restrict__ y_lo,
               __half* __restrict__ yh,
               int M, int K, int N) {
    extern __shared__ __align__(16) char smem[];
    const uint32_t sbase = smem_to_u32(smem);

    const int tid  = threadIdx.x;
    const int wid  = tid >> 5;
    const int lane = tid & 31;
    const int n0 = blockIdx.x * 32;
    const int m0 = blockIdx.y * 32;

    // ---- single load phase: 4096 cp.async total (32 per thread) ----
    {
        #pragma unroll
        for (int u = 0; u < 32; ++u) {
            int i = tid + u * 128;
            int plane = i >> 10;
            int rem = i & 1023;
            int row = rem >> 5;
            int seg = rem & 31;
            uint32_t soff = (uint32_t)(plane * (32 * MLDSB) + row * MLDSB + seg * 16);
            const __nv_bfloat16* src;
            long gofs;
            if (plane < 2) {
                int m = m0 + row; if (m >= M) m = M - 1;
                gofs = (long)m * K + seg * 8;
                src = (plane == 0) ? x_hi : x_lo;
            } else {
                gofs = (long)(n0 + row) * K + seg * 8;
                src = (plane == 2) ? w_hi : w_lo;
            }
            cp16(sbase + soff, src + gofs);
        }
        asm volatile("cp.async.commit_group;" ::: "memory");
        asm volatile("cp.async.wait_group 0;" ::: "memory");
        __syncthreads();
    }

    const uint32_t ah_s = sbase + MT_A_HI;
    const uint32_t al_s = sbase + MT_A_LO;
    const uint32_t wh_s = sbase + MT_W_HI;
    const uint32_t wl_s = sbase + MT_W_LO;

    float c[2][4] = {};   // warp tile 32m x 8n

    #pragma unroll
    for (int kk = 0; kk < MK; kk += 16) {
        uint32_t ah[2][4], al[2][4];
        #pragma unroll
        for (int mi = 0; mi < 2; ++mi) {
            int row = mi * 16 + (lane & 15);
            int col = kk + ((lane >> 4) << 3);
            uint32_t addr = (uint32_t)(row * MLDSB + col * 2);
            ldmatrix_x4(ah[mi], ah_s + addr);
            ldmatrix_x4(al[mi], al_s + addr);
        }
        uint32_t bh[2], bl[2];
        {
            int row = wid * 8 + (lane & 7);
            int col = kk + ((lane >> 3) & 1) * 8;
            uint32_t addr = (uint32_t)(row * MLDSB + col * 2);
            ldmatrix_x2(bh, wh_s + addr);
            ldmatrix_x2(bl, wl_s + addr);
        }
        #pragma unroll
        for (int mi = 0; mi < 2; ++mi) {
            mma_bf16(c[mi], ah[mi], bh);
            mma_bf16(c[mi], ah[mi], bl);
            mma_bf16(c[mi], al[mi], bh);
        }
    }

    // ---- epilogue ----
    #pragma unroll
    for (int mi = 0; mi < 2; ++mi) {
        #pragma unroll
        for (int half = 0; half < 2; ++half) {
            int m = m0 + mi * 16 + half * 8 + (lane >> 2);
            if (m >= M) continue;
            int n = n0 + wid * 8 + 2 * (lane & 3);
            float v0 = c[mi][half * 2 + 0] + bias[n];
            float v1 = c[mi][half * 2 + 1] + bias[n + 1];
            if (LAST) {
                *reinterpret_cast<__half2*>(yh + (long)m * N + n) =
                    __floats2half2_rn(v0, v1);
            } else {
                if (RELU) { v0 = fmaxf(v0, 0.f); v1 = fmaxf(v1, 0.f); }
                uint32_t h, l;
                split2(v0, v1, h, l);
                long o = ((long)m * N + n) >> 1;
                reinterpret_cast<uint32_t*>(y_hi)[o] = h;
                reinterpret_cast<uint32_t*>(y_lo)[o] = l;
            }
        }
    }
}

// ============================================================================
// Logits GEMM v3.3: B-persistent, triple-buffered A with KC=64 (half the
// barriers of v3.2), single barrier per chunk, uniform wave G=16.
// 512 threads, 16 warps 4m x 4n, warp tile 32x40.
// ============================================================================
constexpr int LQT  = 160;
constexpr int LF   = 128;
constexpr int LKC  = 64;
constexpr int LDA2 = LKC + 8;    // A fp16 stride (72)
constexpr int LDB2 = 256 + 8;    // B fp16 stride (264), D=256
constexpr int L_B_OFF  = 0;
constexpr int L_B_SZ   = LQT * LDB2 * 2;             // 84480
constexpr int L_A_OFF  = L_B_SZ;
constexpr int L_A_BUF  = LF * LDA2 * 2;              // 18432
constexpr int LOGITS_SMEM = L_A_OFF + 3 * L_A_BUF;   // 139776

__global__ void __launch_bounds__(512, 1)
logits_mma_kernel(const __half* __restrict__ fv_h,   // [B*F, D] fp16
                  const __half* __restrict__ q_h,    // [B*Q, D] fp16
                  const int* __restrict__ fidx,      // [B*F, 3]
                  float* __restrict__ out,
                  const int* __restrict__ width_ptr, int width_imm,
                  int F, int Q, int D, long HWQ) {
    extern __shared__ __align__(16) char smem[];
    const uint32_t sbase = smem_to_u32(smem);

    const int tid  = threadIdx.x;
    const int wid  = tid >> 5;
    const int lane = tid & 31;
    const int qt = blockIdx.x;
    const int g  = blockIdx.y;
    const int G  = gridDim.y;
    const int b  = blockIdx.z;
    const int q0 = qt * LQT;

    const int warp_m = (wid & 3) * 32;       // 4 m-warps x 32 rows
    const int warp_n = (wid >> 2) * 40;      // 4 n-warps x 40 cols

    const long fbase = (long)b * F;
    const long brow0 = (long)b * Q;
    const int Wd = width_ptr ? *width_ptr : width_imm;

    // ---- load persistent B tile: 160 q-rows x full K (clamped) ----
    {
        const int kq = D >> 3;                       // 16B ops per row (32)
        for (int i = tid; i < LQT * kq; i += 512) {
            int row = i / kq;
            int seg = (i - row * kq) * 8;
            int q = q0 + row;
            if (q >= Q) q = Q - 1;                   // masked in epilogue
            cp16(sbase + L_B_OFF + (uint32_t)((row * LDB2 + seg) * 2),
                 q_h + (brow0 + q) * (long)D + seg);
        }
        asm volatile("cp.async.commit_group;" ::: "memory");
    }

    const int nsub = F / LF;
    const int nmy = (g < nsub) ? (nsub - 1 - g) / G + 1 : 0;
    const int NCH = 256 / LKC;                       // 4 chunks per subtile
    const int T = nmy * NCH;

    auto load_A = [&](int t) {
        int i_sub = t >> 2, kc = t & 3, buf = t % 3;
        long f0 = (long)(g + i_sub * G) * LF;
        // 128 rows x 64 fp16 = 1024 x 16B ops, 2 per thread
        #pragma unroll
        for (int u = 0; u < 2; ++u) {
            int i = tid + u * 512;
            int row = i >> 3;                        // 0..127
            int seg = (i & 7) * 8;
            long gg = (fbase + f0 + row) * D + kc * LKC + seg;
            cp16(sbase + L_A_OFF + (uint32_t)buf * L_A_BUF +
                     (uint32_t)((row * LDA2 + seg) * 2),
                 fv_h + gg);
        }
        asm volatile("cp.async.commit_group;" ::: "memory");
    };

    if (T > 0) load_A(0);
    if (T > 1) load_A(1);

    int t = 0;
    for (int i = 0; i < nmy; ++i) {
        const int f0 = (g + i * G) * LF;

        // prefetch scatter indices for this subtile
        int hh[4], ww[4];
        #pragma unroll
        for (int mi = 0; mi < 2; ++mi) {
            #pragma unroll
            for (int half = 0; half < 2; ++half) {
                int row = warp_m + mi * 16 + half * 8 + (lane >> 2);
                long n = fbase + f0 + row;
                hh[mi * 2 + half] = fidx[3 * n + 1];
                ww[mi * 2 + half] = fidx[3 * n + 2];
            }
        }

        float c[2][5][4] = {};

        for (int kc = 0; kc < NCH; ++kc, ++t) {
            if (t + 1 < T) {
                asm volatile("cp.async.wait_group 1;" ::: "memory");
            } else {
                asm volatile("cp.async.wait_group 0;" ::: "memory");
            }
            __syncthreads();                          // single barrier per chunk
            if (t + 2 < T) load_A(t + 2);             // buf (t-1)%3 is idle

            const uint32_t as = sbase + L_A_OFF + (uint32_t)(t % 3) * L_A_BUF;

            #pragma unroll
            for (int kk = 0; kk < LKC; kk += 16) {
                uint32_t a[2][4];
                #pragma unroll
                for (int mi = 0; mi < 2; ++mi) {
                    int row = warp_m + mi * 16 + (lane & 15);
                    int col = kk + ((lane >> 4) << 3);
                    ldmatrix_x4(a[mi], as + (uint32_t)((row * LDA2 + col) * 2));
                }
                uint32_t bf[5][2];
                {
                    int col = kc * LKC + kk + ((lane >> 3) & 1) * 8;
                    int r1 = warp_n + ((lane & 16) >> 1) + (lane & 7);
                    uint32_t r[4];
                    ldmatrix_x4(r, sbase + L_B_OFF +
                                       (uint32_t)((r1 * LDB2 + col) * 2));
                    bf[0][0] = r[0]; bf[0][1] = r[1];
                    bf[1][0] = r[2]; bf[1][1] = r[3];
                    ldmatrix_x4(r, sbase + L_B_OFF +
                                       (uint32_t)(((r1 + 16) * LDB2 + col) * 2));
                    bf[2][0] = r[0]; bf[2][1] = r[1];
                    bf[3][0] = r[2]; bf[3][1] = r[3];
                    int r2 = warp_n + 32 + (lane & 7);
                    ldmatrix_x2(bf[4], sbase + L_B_OFF +
                                           (uint32_t)((r2 * LDB2 + col) * 2));
                }
                #pragma unroll
                for (int mi = 0; mi < 2; ++mi) {
                    #pragma unroll
                    for (int ni = 0; ni < 5; ++ni) {
                        mma_f16(c[mi][ni], a[mi], bf[ni]);
                    }
                }
            }
        }

        // ---- epilogue for this subtile: lane-paired float4 atomics ----
        #pragma unroll
        for (int mi = 0; mi < 2; ++mi) {
            #pragma unroll
            for (int half = 0; half < 2; ++half) {
                int row = warp_m + mi * 16 + half * 8 + (lane >> 2);
                int f = f0 + row;
                bool ok = (f < F);
                long obase = (long)b * HWQ +
                             ((long)hh[mi * 2 + half] * Wd + ww[mi * 2 + half]) *
                                 (long)Q;
                #pragma unroll
                for (int ni = 0; ni < 5; ++ni) {
                    float v0 = c[mi][ni][half * 2 + 0];
                    float v1 = c[mi][ni][half * 2 + 1];
                    float p0 = __shfl_xor_sync(0xFFFFFFFFu, v0, 1);
                    float p1 = __shfl_xor_sync(0xFFFFFFFFu, v1, 1);
                    if (ok && (lane & 1) == 0) {
                        int q = q0 + warp_n + ni * 8 + 2 * (lane & 3);
                        if (q + 3 < Q) {
                            atomicAdd(reinterpret_cast<float4*>(out + obase + q),
                                      make_float4(v0, v1, p0, p1));
                        } else {
                            if (q     < Q) atomicAdd(out + obase + q,     v0);
                            if (q + 1 < Q) atomicAdd(out + obase + q + 1, v1);
                            if (q + 2 < Q) atomicAdd(out + obase + q + 2, p0);
                            if (q + 3 < Q) atomicAdd(out + obase + q + 3, p1);
                        }
                    }
                }
            }
        }
    }
}

// ---------------------------------------------------------------------------
static int isqrt_host(long v) {
    int r = (int)(sqrt((double)v) + 0.5);
    while ((long)r * r > v) --r;
    while ((long)(r + 1) * (r + 1) <= v) ++r;
    return r;
}

extern "C" void kernel_launch(void* const* d_in, const int* in_sizes, int n_in,
                              void* d_out, int out_size) {
    const float* queries = (const float*)d_in[0];
    const float* fv      = (const float*)d_in[1];
    const int*   fidx    = (const int*)d_in[2];

    bool scalars_present = (n_in >= 15 && in_sizes[5] == 1 && in_sizes[6] == 1);
    int wbase = scalars_present ? 7 : 5;
    const int* width_ptr = scalars_present ? (const int*)d_in[6] : nullptr;

    const float* Wl[4];
    const float* bl[4];
    for (int i = 0; i < 4; ++i) {
        Wl[i] = (const float*)d_in[wbase + 2 * i];
        bl[i] = (const float*)d_in[wbase + 2 * i + 1];
    }

    const int D  = in_sizes[wbase + 1];       // len(b0)
    const int Mq = in_sizes[0] / D;           // B*Q
    const int B  = in_sizes[3] - 1;
    const int Q  = Mq / B;
    const int NF = in_sizes[1] / D;           // B*F
    const int F  = NF / B;
    const long HWQ = (long)out_size / B;      // H*W*Q
    const int width_imm = isqrt_host(HWQ / Q);

    __half *fv_h = nullptr, *q_h = nullptr;
    __nv_bfloat16 *x0h = nullptr, *x0l = nullptr, *x1h = nullptr, *x1l = nullptr;
    __nv_bfloat16 *wh = nullptr, *wl = nullptr;
    cudaGetSymbolAddress((void**)&fv_h, g_fv_h);
    cudaGetSymbolAddress((void**)&q_h, g_q_h);
    cudaGetSymbolAddress((void**)&x0h, g_x0_hi);
    cudaGetSymbolAddress((void**)&x0l, g_x0_lo);
    cudaGetSymbolAddress((void**)&x1h, g_x1_hi);
    cudaGetSymbolAddress((void**)&x1l, g_x1_lo);
    cudaGetSymbolAddress((void**)&wh, g_w_hi);
    cudaGetSymbolAddress((void**)&wl, g_w_lo);

    static cudaStream_t side1 = nullptr, side2 = nullptr;
    static cudaEvent_t ev_fork = nullptr, ev_j1 = nullptr, ev_j2 = nullptr;
    static bool attr_done = false;
    if (!side1) {
        cudaStreamCreateWithFlags(&side1, cudaStreamNonBlocking);
        cudaStreamCreateWithFlags(&side2, cudaStreamNonBlocking);
        cudaEventCreateWithFlags(&ev_fork, cudaEventDisableTiming);
        cudaEventCreateWithFlags(&ev_j1, cudaEventDisableTiming);
        cudaEventCreateWithFlags(&ev_j2, cudaEventDisableTiming);
    }
    if (!attr_done) {
        cudaFuncSetAttribute(logits_mma_kernel,
                             cudaFuncAttributeMaxDynamicSharedMemorySize,
                             LOGITS_SMEM);
        cudaFuncSetAttribute(mlp_mma_kernel<1, 0>,
                             cudaFuncAttributeMaxDynamicSharedMemorySize,
                             MLP_SMEM);
        cudaFuncSetAttribute(mlp_mma_kernel<0, 1>,
                             cudaFuncAttributeMaxDynamicSharedMemorySize,
                             MLP_SMEM);
        attr_done = true;
    }

    // ---- fork: side1 converts fv -> fp16; side2 zeroes output ----
    cudaEventRecord(ev_fork, 0);
    cudaStreamWaitEvent(side1, ev_fork, 0);
    cudaStreamWaitEvent(side2, ev_fork, 0);
    {
        long n4 = (long)NF * D / 4;
        convert_half_kernel<<<(int)DIV_UP(n4, 256L), 256, 0, side1>>>(fv, fv_h, n4);
    }
    cudaMemsetAsync(d_out, 0, (size_t)out_size * sizeof(float), side2);

    // main: weight split, query split, 4 full-K tensor-core MLP layers
    {
        long w4 = (long)D * D / 4;
        convert_split4_kernel<<<(int)DIV_UP(4 * w4, 256L), 256>>>(
            Wl[0], Wl[1], Wl[2], Wl[3], wh, wl, w4);
    }
    {
        long n4 = (long)Mq * D / 4;
        convert_split_kernel<<<(int)DIV_UP(n4, 256L), 256>>>(queries, x0h, x0l, n4);
    }
    {
        dim3 grid(D / 32, DIV_UP(Mq, 32));
        long wsz = (long)D * D;
        mlp_mma_kernel<1, 0><<<grid, 128, MLP_SMEM>>>(
            x0h, x0l, wh + 0 * wsz, wl + 0 * wsz, bl[0], x1h, x1l, nullptr,
            Mq, D, D);
        mlp_mma_kernel<1, 0><<<grid, 128, MLP_SMEM>>>(
            x1h, x1l, wh + 1 * wsz, wl + 1 * wsz, bl[1], x0h, x0l, nullptr,
            Mq, D, D);
        mlp_mma_kernel<1, 0><<<grid, 128, MLP_SMEM>>>(
            x0h, x0l, wh + 2 * wsz, wl + 2 * wsz, bl[2], x1h, x1l, nullptr,
            Mq, D, D);
        mlp_mma_kernel<0, 1><<<grid, 128, MLP_SMEM>>>(
            x1h, x1l, wh + 3 * wsz, wl + 3 * wsz, bl[3], nullptr, nullptr, q_h,
            Mq, D, D);
    }

    // ---- join ----
    cudaEventRecord(ev_j1, side1);
    cudaEventRecord(ev_j2, side2);
    cudaStreamWaitEvent(0, ev_j1, 0);
    cudaStreamWaitEvent(0, ev_j2, 0);

    // Logits GEMM v3.3 (KC=64, single-barrier chunks) + scatter-add
    {
        int nsub = F / LF;
        int G = nsub / 8;                // 16 for F=16384: 8 subtiles per CTA
        if (G < 1) G = 1;
        dim3 grid(DIV_UP(Q, LQT), G, B);
        logits_mma_kernel<<<grid, 512, LOGITS_SMEM>>>(fv_h, q_h, fidx,
                                                      (float*)d_out,
                                                      width_ptr, width_imm,
                                                      F, Q, D, HWQ);
    }
}